// round 13
// baseline (speedup 1.0000x reference)
#include <cuda_runtime.h>
#include <math.h>

// Problem constants
#define Bn 2
#define Cc 512
#define Hh 64
#define Ww 64
#define Ll 4096            // H*W
#define N2 1024            // (H/2)*(W/2)
#define NHEADS 8
#define DK 64
#define Rr 63
#define ATT_SCALE (1.0f/4096.0f)   // 1/DK^2

typedef unsigned long long u64;

// ---- packed f32x2 helpers (Blackwell sm_103a packed fp32 pipe) -------------
__device__ __forceinline__ u64 pack2(float lo, float hi) {
    u64 r; asm("mov.b64 %0,{%1,%2};" : "=l"(r) : "f"(lo), "f"(hi)); return r;
}
__device__ __forceinline__ float2 unpack2(u64 v) {
    float2 f; asm("mov.b64 {%0,%1},%2;" : "=f"(f.x), "=f"(f.y) : "l"(v)); return f;
}
__device__ __forceinline__ void ffma2(u64& d, u64 a, u64 b) {
    asm("fma.rn.f32x2 %0,%1,%2,%0;" : "+l"(d) : "l"(a), "l"(b));
}
__device__ __forceinline__ void fmul2(u64& d, u64 a) {
    asm("mul.rn.f32x2 %0,%0,%1;" : "+l"(d) : "l"(a));
}

// Scratch (static device globals — no allocation in kernel_launch).
// __align__(16): these are accessed through float4* in the GEMM kernels.
__device__ __align__(16) float g_q[Bn*Cc*Ll];        // q conv output        [B][C][L]
__device__ __align__(16) float g_im[Bn*2048*N2];     // im2col for 2x2 conv  [B][2048][n]
__device__ __align__(16) float g_t[Bn*Cc*N2];        // offset trunk         [B][C][n]
__device__ __align__(16) float g_pos[Bn*N2*2];       // sampling positions   [B][n][(y,x)]
__device__ __align__(16) float g_sm[Bn*Cc*N2];       // sampled x            [B][C][n]
__device__ __align__(16) float g_kv[Bn*2*Cc*N2];     // k|v                  [B][2C][n]
__device__ __align__(16) float g_ao[Bn*Cc*Ll];       // attention output     [B][C][L]

// ---------------------------------------------------------------------------
// Generic SGEMM: Y[M,N] = W[M,K] @ X[K,N] + bias.  64x64 tile, 4x4 microtile,
// 256 threads, k-step 16, DOUBLE-BUFFERED smem (1 sync/iter, loads overlap
// compute).  Inner loop on the packed f32x2 FMA pipe — bit-exact fp32.
// accp[j][h] holds output rows (4*ty+2h, 4*ty+2h+1), column 4*tx+j.
// ---------------------------------------------------------------------------
__global__ void sgemm_bias(const float* __restrict__ W, const float* __restrict__ X,
                           const float* __restrict__ bias, float* __restrict__ Y,
                           int M, int N, int K, long sX, long sY)
{
    const float* Xb = X + (long)blockIdx.z * sX;
    float* Yb = Y + (long)blockIdx.z * sY;
    int m0 = blockIdx.y * 64, n0 = blockIdx.x * 64;
    __shared__ __align__(16) float As[2][16][68];   // [stage][k][m]; 272B rows
    __shared__ __align__(16) float Bs[2][16][64];   // [stage][k][n]; 256B rows
    int tid = threadIdx.x;
    int ai = tid >> 2, aj = (tid & 3) << 2;    // A load: row m0+ai, k offset aj
    int br = tid >> 4, bc = (tid & 15) << 2;   // B load: k row br, col bc
    int ty = tid >> 4, tx = tid & 15;
    u64 accp[4][2] = {};   // zero bits == (0.0f, 0.0f)

    const float* wp = W  + (long)(m0+ai)*K + aj;
    const float* xp = Xb + (long)br*N + n0 + bc;

    // prologue: stage 0
    float4 av = *(const float4*)wp;
    float4 bv = *(const float4*)xp;
    As[0][aj+0][ai]=av.x; As[0][aj+1][ai]=av.y; As[0][aj+2][ai]=av.z; As[0][aj+3][ai]=av.w;
    *(float4*)&Bs[0][br][bc] = bv;
    __syncthreads();

    int nk = K >> 4;
    for (int it = 0; it < nk; it++) {
        int s = it & 1;
        if (it + 1 < nk) {   // issue next tile's gmem loads before compute
            av = *(const float4*)(wp + (it+1)*16);
            bv = *(const float4*)(xp + (long)(it+1)*16*N);
        }
#pragma unroll
        for (int kk = 0; kk < 16; kk++) {
            const u64* ap = (const u64*)&As[s][kk][ty<<2];   // 16B-aligned
            u64 am01 = ap[0], am23 = ap[1];                  // packed m-pairs, free
            float4 bq = *(float4*)&Bs[s][kk][tx<<2];
            u64 b0 = pack2(bq.x, bq.x);   // broadcasts issue on ALU pipe,
            u64 b1 = pack2(bq.y, bq.y);   // dual-issuing against FFMA2
            u64 b2 = pack2(bq.z, bq.z);
            u64 b3 = pack2(bq.w, bq.w);
            ffma2(accp[0][0], am01, b0); ffma2(accp[0][1], am23, b0);
            ffma2(accp[1][0], am01, b1); ffma2(accp[1][1], am23, b1);
            ffma2(accp[2][0], am01, b2); ffma2(accp[2][1], am23, b2);
            ffma2(accp[3][0], am01, b3); ffma2(accp[3][1], am23, b3);
        }
        if (it + 1 < nk) {
            int d = s ^ 1;   // writes to the other stage race nothing
            As[d][aj+0][ai]=av.x; As[d][aj+1][ai]=av.y;
            As[d][aj+2][ai]=av.z; As[d][aj+3][ai]=av.w;
            *(float4*)&Bs[d][br][bc] = bv;
            __syncthreads();   // one sync per iteration
        }
    }
#pragma unroll
    for (int i = 0; i < 4; i++) {
        float bb = bias ? bias[m0+(ty<<2)+i] : 0.0f;
        float* yr = Yb + (long)(m0+(ty<<2)+i)*N + n0 + (tx<<2);
#pragma unroll
        for (int j = 0; j < 4; j++) {
            float2 v = unpack2(accp[j][i>>1]);
            yr[j] = ((i & 1) ? v.y : v.x) + bb;
        }
    }
}

// ---------------------------------------------------------------------------
// im2col for the 2x2 stride-2 conv: im[b][ci*4+ky*2+kx][py*32+px] =
//   q[b][ci][(2py+ky)*64 + 2px+kx]   (matches off1_w [C,C,2,2] layout)
// ---------------------------------------------------------------------------
__global__ void im2col_kernel(const float* __restrict__ q, float* __restrict__ im)
{
    int idx = blockIdx.x * 256 + threadIdx.x;   // exactly B*2048*1024 threads
    int p = idx & 1023;
    int k = (idx >> 10) & 2047;
    int b = idx >> 21;
    int ci = k >> 2, ky = (k >> 1) & 1, kx = k & 1;
    int py = p >> 5, px = p & 31;
    im[idx] = q[((long)b*Cc + ci)*Ll + (2*py+ky)*Ww + 2*px + kx];
}

// ---------------------------------------------------------------------------
// GroupNorm (32 groups of 16 ch x 1024) + exact GELU, in place on g_t.
// One block per (b, group).
// ---------------------------------------------------------------------------
__global__ void gn_gelu_kernel(float* __restrict__ t, const float* __restrict__ w,
                               const float* __restrict__ b)
{
    int bb = blockIdx.x >> 5, g = blockIdx.x & 31;
    float* base = t + ((long)bb*Cc + g*16)*N2;
    int tid = threadIdx.x;
    float s = 0.0f, s2 = 0.0f;
    for (int i = tid; i < 16*N2; i += 256) { float v = base[i]; s += v; s2 += v*v; }
    __shared__ float r1[256], r2[256];
    r1[tid] = s; r2[tid] = s2;
    __syncthreads();
    for (int o = 128; o > 0; o >>= 1) {
        if (tid < o) { r1[tid] += r1[tid+o]; r2[tid] += r2[tid+o]; }
        __syncthreads();
    }
    float mu  = r1[0] * (1.0f/16384.0f);
    float var = r2[0] * (1.0f/16384.0f) - mu*mu;
    float rstd = rsqrtf(var + 1e-5f);
    for (int i = tid; i < 16*N2; i += 256) {
        int c = g*16 + (i >> 10);
        float v = (base[i] - mu) * rstd * w[c] + b[c];
        base[i] = 0.5f * v * (1.0f + erff(v * 0.70710678118654752f));
    }
}

// ---------------------------------------------------------------------------
// offset conv (off2_w [2,512], no bias) + reference grid + clip -> g_pos[b][n][(y,x)]
// One warp per position.
// ---------------------------------------------------------------------------
__global__ void offset_pos_kernel(const float* __restrict__ t, const float* __restrict__ w2,
                                  float* __restrict__ pos)
{
    int gid = blockIdx.x * 8 + (threadIdx.x >> 5);   // b*1024 + n
    int lane = threadIdx.x & 31;
    int b = gid >> 10, n = gid & 1023;
    const float* tb = t + (long)b*Cc*N2 + n;
    float sy = 0.0f, sx = 0.0f;
    for (int c = lane; c < Cc; c += 32) {
        float tv = tb[(long)c*N2];
        sy += w2[c]      * tv;   // channel 0 -> y offset
        sx += w2[Cc + c] * tv;   // channel 1 -> x offset
    }
#pragma unroll
    for (int o = 16; o > 0; o >>= 1) {
        sy += __shfl_down_sync(0xffffffffu, sy, o);
        sx += __shfl_down_sync(0xffffffffu, sx, o);
    }
    if (lane == 0) {
        int iy = n >> 5, ix = n & 31;
        float ry = (0.5f + (float)iy) / 31.0f * 2.0f - 1.0f;
        float rx = (0.5f + (float)ix) / 31.0f * 2.0f - 1.0f;
        pos[gid*2+0] = fminf(fmaxf(sy + ry, -1.0f), 1.0f);
        pos[gid*2+1] = fminf(fmaxf(sx + rx, -1.0f), 1.0f);
    }
}

// ---------------------------------------------------------------------------
// Bilinear grid_sample of x at pos -> g_sm[b][c][n].  One block per (b,n).
// ---------------------------------------------------------------------------
__global__ void sample_kernel(const float* __restrict__ x, const float* __restrict__ pos,
                              float* __restrict__ sm)
{
    int gid = blockIdx.x;
    int b = gid >> 10, n = gid & 1023;
    float py = pos[gid*2+0], px = pos[gid*2+1];
    float fx = (px + 1.0f) * 0.5f * 63.0f;
    float fy = (py + 1.0f) * 0.5f * 63.0f;
    float x0f = floorf(fx), y0f = floorf(fy);
    float wx = fx - x0f, wy = fy - y0f;
    int x0 = min(max((int)x0f, 0), 63), y0 = min(max((int)y0f, 0), 63);
    int x1 = min(x0+1, 63), y1 = min(y0+1, 63);
    float w00 = (1.0f-wx)*(1.0f-wy), w01 = wx*(1.0f-wy);
    float w10 = (1.0f-wx)*wy,        w11 = wx*wy;
    const float* xb = x + (long)b*Cc*Ll;
    for (int c = threadIdx.x; c < Cc; c += 128) {
        const float* xc = xb + (long)c*Ll;
        float v = xc[y0*64+x0]*w00 + xc[y0*64+x1]*w01
                + xc[y1*64+x0]*w10 + xc[y1*64+x1]*w11;
        sm[((long)b*Cc + c)*N2 + n] = v;
    }
}

// ---------------------------------------------------------------------------
// Fused attention: QK^T*scale + bilinear RPE bias + online softmax + PV.
// One thread per query (128 queries/block), K/V staged n-major in smem,
// head RPE table (63x63) in smem.  Dot and PV run on the packed f32x2 pipe.
// __launch_bounds__(128,2): 2 blocks/SM -> 2 warps/SMSP so one warp's FFMA2
// bursts hide the other's scalar softmax/RPE tail.
// ---------------------------------------------------------------------------
__global__ __launch_bounds__(128, 2)
void attn_kernel(const float* __restrict__ q, const float* __restrict__ kv,
                 const float* __restrict__ pos, const float* __restrict__ rpe,
                 float* __restrict__ out)
{
    int bh = blockIdx.y; int b = bh >> 3, h = bh & 7;
    int m = blockIdx.x * 128 + threadIdx.x;
    __shared__ __align__(16) float Ks[32][68];   // [n-in-tile][dk]; 272B rows (16B mult)
    __shared__ __align__(16) float Vs[32][68];
    __shared__ float rs[Rr*Rr];
    __shared__ float ps[64];       // pos (y,x) for the n-tile
    const float* rh = rpe + h*Rr*Rr;
    for (int i = threadIdx.x; i < Rr*Rr; i += 128) rs[i] = rh[i];

    const float* qb = q + ((long)b*Cc + h*DK)*Ll + m;
    u64 q2[32];                    // packed, pre-scaled by 1/DK^2
#pragma unroll
    for (int d2 = 0; d2 < 32; d2++)
        q2[d2] = pack2(qb[(2*d2+0)*Ll] * ATT_SCALE, qb[(2*d2+1)*Ll] * ATT_SCALE);
    float qgy = (float)(m >> 6) / 63.0f * 2.0f - 1.0f;
    float qgx = (float)(m & 63) / 63.0f * 2.0f - 1.0f;

    u64 ac2[32] = {};              // packed PV accumulator (zero bits == 0.0f pair)
    float runM = -1e30f, Z = 0.0f;

    const float* kbase = kv + ((long)b*2*Cc + h*DK)*N2;
    const float* vbase = kbase + (long)Cc*N2;
    const float* pb = pos + b*N2*2;

    for (int n0 = 0; n0 < N2; n0 += 32) {
        __syncthreads();
        for (int e = threadIdx.x; e < 2048; e += 128) {
            int d = e >> 5, j = e & 31;
            Ks[j][d] = kbase[d*N2 + n0 + j];
            Vs[j][d] = vbase[d*N2 + n0 + j];
        }
        if (threadIdx.x < 64) ps[threadIdx.x] = pb[n0*2 + threadIdx.x];
        __syncthreads();

        for (int j = 0; j < 32; j++) {
            const ulonglong2* kp = (const ulonglong2*)Ks[j];   // LDS.128 pairs
            u64 dp[4] = {};
#pragma unroll
            for (int t = 0; t < 16; t++) {
                ulonglong2 kk2 = kp[t];
                ffma2(dp[(2*t)   & 3], q2[2*t],   kk2.x);
                ffma2(dp[(2*t+1) & 3], q2[2*t+1], kk2.y);
            }
            float2 s0 = unpack2(dp[0]), s1 = unpack2(dp[1]);
            float2 s2 = unpack2(dp[2]), s3 = unpack2(dp[3]);
            float dot = ((s0.x+s0.y) + (s1.x+s1.y)) + ((s2.x+s2.y) + (s3.x+s3.y));
            // RPE bias: bilinear sample of rs at disp=((qg - pos)*0.5), R=63
            float dy = (qgy - ps[j*2+0]) * 0.5f;
            float dx = (qgx - ps[j*2+1]) * 0.5f;
            float fy = (dy + 1.0f) * 0.5f * 62.0f;
            float fx = (dx + 1.0f) * 0.5f * 62.0f;
            float y0f = floorf(fy), x0f = floorf(fx);
            float wy = fy - y0f, wx = fx - x0f;
            int y0 = min(max((int)y0f, 0), 62);
            int x0 = min(max((int)x0f, 0), 62);
            int y1 = min(y0 + 1, 62), x1 = min(x0 + 1, 62);
            float r00 = rs[y0*63+x0], r01 = rs[y0*63+x1];
            float r10 = rs[y1*63+x0], r11 = rs[y1*63+x1];
            float bia = r00*(1.0f-wx)*(1.0f-wy) + r01*wx*(1.0f-wy)
                      + r10*(1.0f-wx)*wy       + r11*wx*wy;
            float s = dot + bia;
            if (s > runM) {   // rare for this data (near-uniform logits)
                float corr = __expf(runM - s);
                Z *= corr;
                u64 c2 = pack2(corr, corr);
#pragma unroll
                for (int c = 0; c < 32; c++) fmul2(ac2[c], c2);
                runM = s;
            }
            float p = __expf(s - runM);
            Z += p;
            u64 p2 = pack2(p, p);
            const ulonglong2* vp = (const ulonglong2*)Vs[j];
#pragma unroll
            for (int t = 0; t < 16; t++) {
                ulonglong2 vv = vp[t];
                ffma2(ac2[2*t],   p2, vv.x);
                ffma2(ac2[2*t+1], p2, vv.y);
            }
        }
    }
    float inv = 1.0f / Z;
    float* ob = out + ((long)b*Cc + h*DK)*Ll + m;
#pragma unroll
    for (int d2 = 0; d2 < 32; d2++) {
        float2 v = unpack2(ac2[d2]);
        ob[(long)(2*d2+0)*Ll] = v.x * inv;
        ob[(long)(2*d2+1)*Ll] = v.y * inv;
    }
}

// ---------------------------------------------------------------------------
extern "C" void kernel_launch(void* const* d_in, const int* in_sizes, int n_in,
                              void* d_out, int out_size)
{
    const float* x      = (const float*)d_in[0];
    const float* q_w    = (const float*)d_in[1];
    const float* q_b    = (const float*)d_in[2];
    const float* kv_w   = (const float*)d_in[3];
    const float* kv_b   = (const float*)d_in[4];
    const float* off1_w = (const float*)d_in[5];
    const float* off1_b = (const float*)d_in[6];
    const float* gn_w   = (const float*)d_in[7];
    const float* gn_b   = (const float*)d_in[8];
    const float* off2_w = (const float*)d_in[9];
    const float* rpe    = (const float*)d_in[10];
    const float* proj_w = (const float*)d_in[11];
    const float* proj_b = (const float*)d_in[12];
    float* out = (float*)d_out;

    float *gq, *gim, *gt, *gpos, *gsm, *gkv, *gao;
    cudaGetSymbolAddress((void**)&gq,   g_q);
    cudaGetSymbolAddress((void**)&gim,  g_im);
    cudaGetSymbolAddress((void**)&gt,   g_t);
    cudaGetSymbolAddress((void**)&gpos, g_pos);
    cudaGetSymbolAddress((void**)&gsm,  g_sm);
    cudaGetSymbolAddress((void**)&gkv,  g_kv);
    cudaGetSymbolAddress((void**)&gao,  g_ao);

    // 1. q = conv1x1(x)
    sgemm_bias<<<dim3(64,8,2),256>>>(q_w, x, q_b, gq, 512, 4096, 512,
                                     (long)512*4096, (long)512*4096);
    // 2. im2col for 2x2 stride-2 conv
    im2col_kernel<<<16384,256>>>(gq, gim);
    // 3. t = conv2x2s2(q)
    sgemm_bias<<<dim3(16,8,2),256>>>(off1_w, gim, off1_b, gt, 512, 1024, 2048,
                                     (long)2048*1024, (long)512*1024);
    // 4. GroupNorm + GELU (in place)
    gn_gelu_kernel<<<64,256>>>(gt, gn_w, gn_b);
    // 5. offset conv + reference grid + clip -> pos
    offset_pos_kernel<<<256,256>>>(gt, off2_w, gpos);
    // 6. bilinear sample of x at pos
    sample_kernel<<<2048,128>>>(x, gpos, gsm);
    // 7. kv = conv1x1(sampled)
    sgemm_bias<<<dim3(16,16,2),256>>>(kv_w, gsm, kv_b, gkv, 1024, 1024, 512,
                                      (long)512*1024, (long)1024*1024);
    // 8. fused attention (QK^T + RPE bias + softmax + PV)
    attn_kernel<<<dim3(32,16),128>>>(gq, gkv, gpos, rpe, gao);
    // 9. proj conv -> d_out
    sgemm_bias<<<dim3(64,8,2),256>>>(proj_w, gao, proj_b, out, 512, 4096, 512,
                                     (long)512*4096, (long)512*4096);
}

// round 14
// speedup vs baseline: 1.5796x; 1.5796x over previous
#include <cuda_runtime.h>
#include <math.h>

// Problem constants
#define Bn 2
#define Cc 512
#define Hh 64
#define Ww 64
#define Ll 4096            // H*W
#define N2 1024            // (H/2)*(W/2)
#define NHEADS 8
#define DK 64
#define Rr 63
#define ATT_SCALE (1.0f/4096.0f)   // 1/DK^2

typedef unsigned long long u64;

// ---- packed f32x2 helpers (Blackwell sm_103a packed fp32 pipe) -------------
__device__ __forceinline__ u64 pack2(float lo, float hi) {
    u64 r; asm("mov.b64 %0,{%1,%2};" : "=l"(r) : "f"(lo), "f"(hi)); return r;
}
__device__ __forceinline__ float2 unpack2(u64 v) {
    float2 f; asm("mov.b64 {%0,%1},%2;" : "=f"(f.x), "=f"(f.y) : "l"(v)); return f;
}
__device__ __forceinline__ void ffma2(u64& d, u64 a, u64 b) {
    asm("fma.rn.f32x2 %0,%1,%2,%0;" : "+l"(d) : "l"(a), "l"(b));
}
__device__ __forceinline__ void fmul2(u64& d, u64 a) {
    asm("mul.rn.f32x2 %0,%0,%1;" : "+l"(d) : "l"(a));
}

// Scratch (static device globals — no allocation in kernel_launch).
// __align__(16): these are accessed through float4* in the GEMM kernels.
__device__ __align__(16) float g_q[Bn*Cc*Ll];        // q conv output        [B][C][L]
__device__ __align__(16) float g_im[Bn*2048*N2];     // im2col for 2x2 conv  [B][2048][n]
__device__ __align__(16) float g_t[Bn*Cc*N2];        // offset trunk         [B][C][n]
__device__ __align__(16) float g_pos[Bn*N2*2];       // sampling positions   [B][n][(y,x)]
__device__ __align__(16) float g_sm[Bn*Cc*N2];       // sampled x            [B][C][n]
__device__ __align__(16) float g_kv[Bn*2*Cc*N2];     // k|v                  [B][2C][n]
__device__ __align__(16) float g_ao[Bn*Cc*Ll];       // attention output     [B][C][L]

// ---------------------------------------------------------------------------
// Generic SGEMM (exact R11 version — known good): Y[M,N] = W[M,K] @ X[K,N] +
// bias.  64x64 tile, 4x4 microtile, 256 threads, k-step 16, inner loop on the
// packed f32x2 FMA pipe.
// ---------------------------------------------------------------------------
__global__ void sgemm_bias(const float* __restrict__ W, const float* __restrict__ X,
                           const float* __restrict__ bias, float* __restrict__ Y,
                           int M, int N, int K, long sX, long sY)
{
    const float* Xb = X + (long)blockIdx.z * sX;
    float* Yb = Y + (long)blockIdx.z * sY;
    int m0 = blockIdx.y * 64, n0 = blockIdx.x * 64;
    __shared__ __align__(16) float As[16][68];   // A transposed: As[k][m]; 272B rows (16B mult)
    __shared__ __align__(16) float Bs[16][64];   // 256B rows
    int tid = threadIdx.x;
    int ai = tid >> 2, aj = (tid & 3) << 2;    // A load: row m0+ai, k offset aj
    int br = tid >> 4, bc = (tid & 15) << 2;   // B load: k row br, col bc
    int ty = tid >> 4, tx = tid & 15;
    u64 accp[4][2] = {};   // zero bits == (0.0f, 0.0f)
    for (int k0 = 0; k0 < K; k0 += 16) {
        float4 av = *(const float4*)(W  + (long)(m0+ai)*K + k0 + aj);
        float4 bv = *(const float4*)(Xb + (long)(k0+br)*N + n0 + bc);
        __syncthreads();   // previous compute done before overwriting smem
        As[aj+0][ai]=av.x; As[aj+1][ai]=av.y; As[aj+2][ai]=av.z; As[aj+3][ai]=av.w;
        *(float4*)&Bs[br][bc] = bv;
        __syncthreads();
#pragma unroll
        for (int kk = 0; kk < 16; kk++) {
            const u64* ap = (const u64*)&As[kk][ty<<2];   // 16B-aligned (272B rows)
            u64 am01 = ap[0], am23 = ap[1];               // packed m-pairs, free
            float4 bq = *(float4*)&Bs[kk][tx<<2];
            u64 b0 = pack2(bq.x, bq.x);   // broadcasts issue on ALU pipe,
            u64 b1 = pack2(bq.y, bq.y);   // dual-issuing against FFMA2
            u64 b2 = pack2(bq.z, bq.z);
            u64 b3 = pack2(bq.w, bq.w);
            ffma2(accp[0][0], am01, b0); ffma2(accp[0][1], am23, b0);
            ffma2(accp[1][0], am01, b1); ffma2(accp[1][1], am23, b1);
            ffma2(accp[2][0], am01, b2); ffma2(accp[2][1], am23, b2);
            ffma2(accp[3][0], am01, b3); ffma2(accp[3][1], am23, b3);
        }
    }
#pragma unroll
    for (int i = 0; i < 4; i++) {
        float bb = bias ? bias[m0+(ty<<2)+i] : 0.0f;
        float* yr = Yb + (long)(m0+(ty<<2)+i)*N + n0 + (tx<<2);
#pragma unroll
        for (int j = 0; j < 4; j++) {
            float2 v = unpack2(accp[j][i>>1]);
            yr[j] = ((i & 1) ? v.y : v.x) + bb;
        }
    }
}

// ---------------------------------------------------------------------------
// im2col for the 2x2 stride-2 conv: im[b][ci*4+ky*2+kx][py*32+px] =
//   q[b][ci][(2py+ky)*64 + 2px+kx]   (matches off1_w [C,C,2,2] layout)
// ---------------------------------------------------------------------------
__global__ void im2col_kernel(const float* __restrict__ q, float* __restrict__ im)
{
    int idx = blockIdx.x * 256 + threadIdx.x;   // exactly B*2048*1024 threads
    int p = idx & 1023;
    int k = (idx >> 10) & 2047;
    int b = idx >> 21;
    int ci = k >> 2, ky = (k >> 1) & 1, kx = k & 1;
    int py = p >> 5, px = p & 31;
    im[idx] = q[((long)b*Cc + ci)*Ll + (2*py+ky)*Ww + 2*px + kx];
}

// ---------------------------------------------------------------------------
// GroupNorm (32 groups of 16 ch x 1024) + exact GELU, in place on g_t.
// One block per (b, group).  [Also serves as the cross-round clock canary.]
// ---------------------------------------------------------------------------
__global__ void gn_gelu_kernel(float* __restrict__ t, const float* __restrict__ w,
                               const float* __restrict__ b)
{
    int bb = blockIdx.x >> 5, g = blockIdx.x & 31;
    float* base = t + ((long)bb*Cc + g*16)*N2;
    int tid = threadIdx.x;
    float s = 0.0f, s2 = 0.0f;
    for (int i = tid; i < 16*N2; i += 256) { float v = base[i]; s += v; s2 += v*v; }
    __shared__ float r1[256], r2[256];
    r1[tid] = s; r2[tid] = s2;
    __syncthreads();
    for (int o = 128; o > 0; o >>= 1) {
        if (tid < o) { r1[tid] += r1[tid+o]; r2[tid] += r2[tid+o]; }
        __syncthreads();
    }
    float mu  = r1[0] * (1.0f/16384.0f);
    float var = r2[0] * (1.0f/16384.0f) - mu*mu;
    float rstd = rsqrtf(var + 1e-5f);
    for (int i = tid; i < 16*N2; i += 256) {
        int c = g*16 + (i >> 10);
        float v = (base[i] - mu) * rstd * w[c] + b[c];
        base[i] = 0.5f * v * (1.0f + erff(v * 0.70710678118654752f));
    }
}

// ---------------------------------------------------------------------------
// offset conv (off2_w [2,512], no bias) + reference grid + clip -> g_pos[b][n][(y,x)]
// One warp per position.
// ---------------------------------------------------------------------------
__global__ void offset_pos_kernel(const float* __restrict__ t, const float* __restrict__ w2,
                                  float* __restrict__ pos)
{
    int gid = blockIdx.x * 8 + (threadIdx.x >> 5);   // b*1024 + n
    int lane = threadIdx.x & 31;
    int b = gid >> 10, n = gid & 1023;
    const float* tb = t + (long)b*Cc*N2 + n;
    float sy = 0.0f, sx = 0.0f;
    for (int c = lane; c < Cc; c += 32) {
        float tv = tb[(long)c*N2];
        sy += w2[c]      * tv;   // channel 0 -> y offset
        sx += w2[Cc + c] * tv;   // channel 1 -> x offset
    }
#pragma unroll
    for (int o = 16; o > 0; o >>= 1) {
        sy += __shfl_down_sync(0xffffffffu, sy, o);
        sx += __shfl_down_sync(0xffffffffu, sx, o);
    }
    if (lane == 0) {
        int iy = n >> 5, ix = n & 31;
        float ry = (0.5f + (float)iy) / 31.0f * 2.0f - 1.0f;
        float rx = (0.5f + (float)ix) / 31.0f * 2.0f - 1.0f;
        pos[gid*2+0] = fminf(fmaxf(sy + ry, -1.0f), 1.0f);
        pos[gid*2+1] = fminf(fmaxf(sx + rx, -1.0f), 1.0f);
    }
}

// ---------------------------------------------------------------------------
// Bilinear grid_sample of x at pos -> g_sm[b][c][n].  One block per (b,n).
// ---------------------------------------------------------------------------
__global__ void sample_kernel(const float* __restrict__ x, const float* __restrict__ pos,
                              float* __restrict__ sm)
{
    int gid = blockIdx.x;
    int b = gid >> 10, n = gid & 1023;
    float py = pos[gid*2+0], px = pos[gid*2+1];
    float fx = (px + 1.0f) * 0.5f * 63.0f;
    float fy = (py + 1.0f) * 0.5f * 63.0f;
    float x0f = floorf(fx), y0f = floorf(fy);
    float wx = fx - x0f, wy = fy - y0f;
    int x0 = min(max((int)x0f, 0), 63), y0 = min(max((int)y0f, 0), 63);
    int x1 = min(x0+1, 63), y1 = min(y0+1, 63);
    float w00 = (1.0f-wx)*(1.0f-wy), w01 = wx*(1.0f-wy);
    float w10 = (1.0f-wx)*wy,        w11 = wx*wy;
    const float* xb = x + (long)b*Cc*Ll;
    for (int c = threadIdx.x; c < Cc; c += 128) {
        const float* xc = xb + (long)c*Ll;
        float v = xc[y0*64+x0]*w00 + xc[y0*64+x1]*w01
                + xc[y1*64+x0]*w10 + xc[y1*64+x1]*w11;
        sm[((long)b*Cc + c)*N2 + n] = v;
    }
}

// ---------------------------------------------------------------------------
// Fused attention: QK^T*scale + bilinear RPE bias + online softmax + PV.
// One thread per query (128 queries/block), K/V staged n-major in smem,
// head RPE table (63x63) in smem.  Dot and PV run on the packed f32x2 pipe.
// __launch_bounds__(128,2): 2 blocks/SM -> 2 warps/SMSP so one warp's FFMA2
// bursts hide the other's scalar softmax/RPE tail.  (ONLY change vs R11.)
// ---------------------------------------------------------------------------
__global__ __launch_bounds__(128, 2)
void attn_kernel(const float* __restrict__ q, const float* __restrict__ kv,
                 const float* __restrict__ pos, const float* __restrict__ rpe,
                 float* __restrict__ out)
{
    int bh = blockIdx.y; int b = bh >> 3, h = bh & 7;
    int m = blockIdx.x * 128 + threadIdx.x;
    __shared__ __align__(16) float Ks[32][68];   // [n-in-tile][dk]; 272B rows (16B mult)
    __shared__ __align__(16) float Vs[32][68];
    __shared__ float rs[Rr*Rr];
    __shared__ float ps[64];       // pos (y,x) for the n-tile
    const float* rh = rpe + h*Rr*Rr;
    for (int i = threadIdx.x; i < Rr*Rr; i += 128) rs[i] = rh[i];

    const float* qb = q + ((long)b*Cc + h*DK)*Ll + m;
    u64 q2[32];                    // packed, pre-scaled by 1/DK^2
#pragma unroll
    for (int d2 = 0; d2 < 32; d2++)
        q2[d2] = pack2(qb[(2*d2+0)*Ll] * ATT_SCALE, qb[(2*d2+1)*Ll] * ATT_SCALE);
    float qgy = (float)(m >> 6) / 63.0f * 2.0f - 1.0f;
    float qgx = (float)(m & 63) / 63.0f * 2.0f - 1.0f;

    u64 ac2[32] = {};              // packed PV accumulator (zero bits == 0.0f pair)
    float runM = -1e30f, Z = 0.0f;

    const float* kbase = kv + ((long)b*2*Cc + h*DK)*N2;
    const float* vbase = kbase + (long)Cc*N2;
    const float* pb = pos + b*N2*2;

    for (int n0 = 0; n0 < N2; n0 += 32) {
        __syncthreads();
        for (int e = threadIdx.x; e < 2048; e += 128) {
            int d = e >> 5, j = e & 31;
            Ks[j][d] = kbase[d*N2 + n0 + j];
            Vs[j][d] = vbase[d*N2 + n0 + j];
        }
        if (threadIdx.x < 64) ps[threadIdx.x] = pb[n0*2 + threadIdx.x];
        __syncthreads();

        for (int j = 0; j < 32; j++) {
            const ulonglong2* kp = (const ulonglong2*)Ks[j];   // LDS.128 pairs
            u64 dp[4] = {};
#pragma unroll
            for (int t = 0; t < 16; t++) {
                ulonglong2 kk2 = kp[t];
                ffma2(dp[(2*t)   & 3], q2[2*t],   kk2.x);
                ffma2(dp[(2*t+1) & 3], q2[2*t+1], kk2.y);
            }
            float2 s0 = unpack2(dp[0]), s1 = unpack2(dp[1]);
            float2 s2 = unpack2(dp[2]), s3 = unpack2(dp[3]);
            float dot = ((s0.x+s0.y) + (s1.x+s1.y)) + ((s2.x+s2.y) + (s3.x+s3.y));
            // RPE bias: bilinear sample of rs at disp=((qg - pos)*0.5), R=63
            float dy = (qgy - ps[j*2+0]) * 0.5f;
            float dx = (qgx - ps[j*2+1]) * 0.5f;
            float fy = (dy + 1.0f) * 0.5f * 62.0f;
            float fx = (dx + 1.0f) * 0.5f * 62.0f;
            float y0f = floorf(fy), x0f = floorf(fx);
            float wy = fy - y0f, wx = fx - x0f;
            int y0 = min(max((int)y0f, 0), 62);
            int x0 = min(max((int)x0f, 0), 62);
            int y1 = min(y0 + 1, 62), x1 = min(x0 + 1, 62);
            float r00 = rs[y0*63+x0], r01 = rs[y0*63+x1];
            float r10 = rs[y1*63+x0], r11 = rs[y1*63+x1];
            float bia = r00*(1.0f-wx)*(1.0f-wy) + r01*wx*(1.0f-wy)
                      + r10*(1.0f-wx)*wy       + r11*wx*wy;
            float s = dot + bia;
            if (s > runM) {   // rare for this data (near-uniform logits)
                float corr = __expf(runM - s);
                Z *= corr;
                u64 c2 = pack2(corr, corr);
#pragma unroll
                for (int c = 0; c < 32; c++) fmul2(ac2[c], c2);
                runM = s;
            }
            float p = __expf(s - runM);
            Z += p;
            u64 p2 = pack2(p, p);
            const ulonglong2* vp = (const ulonglong2*)Vs[j];
#pragma unroll
            for (int t = 0; t < 16; t++) {
                ulonglong2 vv = vp[t];
                ffma2(ac2[2*t],   p2, vv.x);
                ffma2(ac2[2*t+1], p2, vv.y);
            }
        }
    }
    float inv = 1.0f / Z;
    float* ob = out + ((long)b*Cc + h*DK)*Ll + m;
#pragma unroll
    for (int d2 = 0; d2 < 32; d2++) {
        float2 v = unpack2(ac2[d2]);
        ob[(long)(2*d2+0)*Ll] = v.x * inv;
        ob[(long)(2*d2+1)*Ll] = v.y * inv;
    }
}

// ---------------------------------------------------------------------------
extern "C" void kernel_launch(void* const* d_in, const int* in_sizes, int n_in,
                              void* d_out, int out_size)
{
    const float* x      = (const float*)d_in[0];
    const float* q_w    = (const float*)d_in[1];
    const float* q_b    = (const float*)d_in[2];
    const float* kv_w   = (const float*)d_in[3];
    const float* kv_b   = (const float*)d_in[4];
    const float* off1_w = (const float*)d_in[5];
    const float* off1_b = (const float*)d_in[6];
    const float* gn_w   = (const float*)d_in[7];
    const float* gn_b   = (const float*)d_in[8];
    const float* off2_w = (const float*)d_in[9];
    const float* rpe    = (const float*)d_in[10];
    const float* proj_w = (const float*)d_in[11];
    const float* proj_b = (const float*)d_in[12];
    float* out = (float*)d_out;

    float *gq, *gim, *gt, *gpos, *gsm, *gkv, *gao;
    cudaGetSymbolAddress((void**)&gq,   g_q);
    cudaGetSymbolAddress((void**)&gim,  g_im);
    cudaGetSymbolAddress((void**)&gt,   g_t);
    cudaGetSymbolAddress((void**)&gpos, g_pos);
    cudaGetSymbolAddress((void**)&gsm,  g_sm);
    cudaGetSymbolAddress((void**)&gkv,  g_kv);
    cudaGetSymbolAddress((void**)&gao,  g_ao);

    // 1. q = conv1x1(x)
    sgemm_bias<<<dim3(64,8,2),256>>>(q_w, x, q_b, gq, 512, 4096, 512,
                                     (long)512*4096, (long)512*4096);
    // 2. im2col for 2x2 stride-2 conv
    im2col_kernel<<<16384,256>>>(gq, gim);
    // 3. t = conv2x2s2(q)
    sgemm_bias<<<dim3(16,8,2),256>>>(off1_w, gim, off1_b, gt, 512, 1024, 2048,
                                     (long)2048*1024, (long)512*1024);
    // 4. GroupNorm + GELU (in place)
    gn_gelu_kernel<<<64,256>>>(gt, gn_w, gn_b);
    // 5. offset conv + reference grid + clip -> pos
    offset_pos_kernel<<<256,256>>>(gt, off2_w, gpos);
    // 6. bilinear sample of x at pos
    sample_kernel<<<2048,128>>>(x, gpos, gsm);
    // 7. kv = conv1x1(sampled)
    sgemm_bias<<<dim3(16,16,2),256>>>(kv_w, gsm, kv_b, gkv, 1024, 1024, 512,
                                      (long)512*1024, (long)1024*1024);
    // 8. fused attention (QK^T + RPE bias + softmax + PV)
    attn_kernel<<<dim3(32,16),128>>>(gq, gkv, gpos, rpe, gao);
    // 9. proj conv -> d_out
    sgemm_bias<<<dim3(64,8,2),256>>>(proj_w, gao, proj_b, out, 512, 4096, 512,
                                     (long)512*4096, (long)512*4096);
}

// round 15
// speedup vs baseline: 1.6339x; 1.0344x over previous
#include <cuda_runtime.h>
#include <math.h>

// Problem constants
#define Bn 2
#define Cc 512
#define Hh 64
#define Ww 64
#define Ll 4096            // H*W
#define N2 1024            // (H/2)*(W/2)
#define NHEADS 8
#define DK 64
#define Rr 63
#define ATT_SCALE (1.0f/4096.0f)   // 1/DK^2

typedef unsigned long long u64;

// ---- packed f32x2 helpers (Blackwell sm_103a packed fp32 pipe) -------------
__device__ __forceinline__ u64 pack2(float lo, float hi) {
    u64 r; asm("mov.b64 %0,{%1,%2};" : "=l"(r) : "f"(lo), "f"(hi)); return r;
}
__device__ __forceinline__ float2 unpack2(u64 v) {
    float2 f; asm("mov.b64 {%0,%1},%2;" : "=f"(f.x), "=f"(f.y) : "l"(v)); return f;
}
__device__ __forceinline__ void ffma2(u64& d, u64 a, u64 b) {
    asm("fma.rn.f32x2 %0,%1,%2,%0;" : "+l"(d) : "l"(a), "l"(b));
}
__device__ __forceinline__ void fmul2(u64& d, u64 a) {
    asm("mul.rn.f32x2 %0,%0,%1;" : "+l"(d) : "l"(a));
}

// ---- tf32 tensor-core helpers ----------------------------------------------
__device__ __forceinline__ unsigned cvt_tf32(float f) {
    unsigned r; asm("cvt.rna.tf32.f32 %0,%1;" : "=r"(r) : "f"(f)); return r;
}
// 3xTF32 split: f = hi + lo (both tf32-representable); dropped lo*lo ~ 6e-8 rel.
__device__ __forceinline__ void split_tf32(float f, unsigned& hi, unsigned& lo) {
    hi = cvt_tf32(f);
    lo = cvt_tf32(f - __uint_as_float(hi));
}
__device__ __forceinline__ void mma8(float* c, const unsigned* a, const unsigned* b) {
    asm("mma.sync.aligned.m16n8k8.row.col.f32.tf32.tf32.f32 "
        "{%0,%1,%2,%3},{%4,%5,%6,%7},{%8,%9},{%0,%1,%2,%3};"
        : "+f"(c[0]), "+f"(c[1]), "+f"(c[2]), "+f"(c[3])
        : "r"(a[0]), "r"(a[1]), "r"(a[2]), "r"(a[3]), "r"(b[0]), "r"(b[1]));
}

// Scratch (static device globals — no allocation in kernel_launch).
__device__ __align__(16) float g_q[Bn*Cc*Ll];        // q conv output        [B][C][L]
__device__ __align__(16) float g_im[Bn*2048*N2];     // im2col for 2x2 conv  [B][2048][n]
__device__ __align__(16) float g_t[Bn*Cc*N2];        // offset trunk         [B][C][n]
__device__ __align__(16) float g_pos[Bn*N2*2];       // sampling positions   [B][n][(y,x)]
__device__ __align__(16) float g_sm[Bn*Cc*N2];       // sampled x            [B][C][n]
__device__ __align__(16) float g_kv[Bn*2*Cc*N2];     // k|v                  [B][2C][n]
__device__ __align__(16) float g_ao[Bn*Cc*Ll];       // attention output     [B][C][L]

// ---------------------------------------------------------------------------
// Tensor-core SGEMM, 3xTF32 (fp32-grade accuracy): Y = W @ X + bias.
// 64x64 block tile, BK=32, 256 threads = 8 warps (2x4 m-x-n), warp tile 32x16,
// mma.sync m16n8k8 tf32, fp32 accum.  Each operand split hi/lo; three MMAs
// (hi*hi + hi*lo + lo*hi) recover fp32-level precision.  Fragment indexing
// identical to the R12 kernel (validated on-device).
// ---------------------------------------------------------------------------
__global__ void sgemm_bias(const float* __restrict__ W, const float* __restrict__ X,
                           const float* __restrict__ bias, float* __restrict__ Y,
                           int M, int N, int K, long sX, long sY)
{
    const float* Xb = X + (long)blockIdx.z * sX;
    float* Yb = Y + (long)blockIdx.z * sY;
    int m0 = blockIdx.y * 64, n0 = blockIdx.x * 64;
    __shared__ __align__(16) unsigned Ah[32][72], Al[32][72];   // tf32 hi/lo, [k][m]
    __shared__ __align__(16) unsigned Bh[32][72], Bl[32][72];   // tf32 hi/lo, [k][n]
    int tid = threadIdx.x;
    int am = tid >> 2, ak = (tid & 3) << 2;    // A: row m0+am, k = ak..ak+3, ak+16..ak+19
    int bk = tid >> 4, bn = (tid & 15) << 2;   // B: k rows bk, bk+16; cols bn..bn+3
    int w = tid >> 5, lane = tid & 31;
    int wm = (w >> 2) << 5, wn = (w & 3) << 4; // warp tile origin (32m x 16n)
    int grp = lane >> 2, tig = lane & 3;
    float acc[2][2][4] = {};                   // [mt][nt][frag]
    for (int k0 = 0; k0 < K; k0 += 32) {
        const float* wp = W + (long)(m0+am)*K + k0 + ak;
        float4 a0v = *(const float4*)wp;
        float4 a1v = *(const float4*)(wp + 16);
        const float* xp = Xb + (long)(k0+bk)*N + n0 + bn;
        float4 b0v = *(const float4*)xp;
        float4 b1v = *(const float4*)(xp + (long)16*N);
        __syncthreads();   // previous compute done before overwriting smem
        split_tf32(a0v.x, Ah[ak+0 ][am], Al[ak+0 ][am]);
        split_tf32(a0v.y, Ah[ak+1 ][am], Al[ak+1 ][am]);
        split_tf32(a0v.z, Ah[ak+2 ][am], Al[ak+2 ][am]);
        split_tf32(a0v.w, Ah[ak+3 ][am], Al[ak+3 ][am]);
        split_tf32(a1v.x, Ah[ak+16][am], Al[ak+16][am]);
        split_tf32(a1v.y, Ah[ak+17][am], Al[ak+17][am]);
        split_tf32(a1v.z, Ah[ak+18][am], Al[ak+18][am]);
        split_tf32(a1v.w, Ah[ak+19][am], Al[ak+19][am]);
        split_tf32(b0v.x, Bh[bk   ][bn+0], Bl[bk   ][bn+0]);
        split_tf32(b0v.y, Bh[bk   ][bn+1], Bl[bk   ][bn+1]);
        split_tf32(b0v.z, Bh[bk   ][bn+2], Bl[bk   ][bn+2]);
        split_tf32(b0v.w, Bh[bk   ][bn+3], Bl[bk   ][bn+3]);
        split_tf32(b1v.x, Bh[bk+16][bn+0], Bl[bk+16][bn+0]);
        split_tf32(b1v.y, Bh[bk+16][bn+1], Bl[bk+16][bn+1]);
        split_tf32(b1v.z, Bh[bk+16][bn+2], Bl[bk+16][bn+2]);
        split_tf32(b1v.w, Bh[bk+16][bn+3], Bl[bk+16][bn+3]);
        __syncthreads();
#pragma unroll
        for (int ks = 0; ks < 4; ks++) {
            int kb = ks << 3;
            unsigned ah[2][4], al[2][4], bh[2][2], bl[2][2];
#pragma unroll
            for (int mt = 0; mt < 2; mt++) {
                int mr = wm + (mt << 4) + grp;
                ah[mt][0] = Ah[kb+tig  ][mr];   al[mt][0] = Al[kb+tig  ][mr];
                ah[mt][1] = Ah[kb+tig  ][mr+8]; al[mt][1] = Al[kb+tig  ][mr+8];
                ah[mt][2] = Ah[kb+tig+4][mr];   al[mt][2] = Al[kb+tig+4][mr];
                ah[mt][3] = Ah[kb+tig+4][mr+8]; al[mt][3] = Al[kb+tig+4][mr+8];
            }
#pragma unroll
            for (int nt = 0; nt < 2; nt++) {
                int nc = wn + (nt << 3) + grp;
                bh[nt][0] = Bh[kb+tig  ][nc];   bl[nt][0] = Bl[kb+tig  ][nc];
                bh[nt][1] = Bh[kb+tig+4][nc];   bl[nt][1] = Bl[kb+tig+4][nc];
            }
#pragma unroll
            for (int mt = 0; mt < 2; mt++)
#pragma unroll
                for (int nt = 0; nt < 2; nt++) {
                    mma8(acc[mt][nt], ah[mt], bl[nt]);   // hi*lo
                    mma8(acc[mt][nt], al[mt], bh[nt]);   // lo*hi
                    mma8(acc[mt][nt], ah[mt], bh[nt]);   // hi*hi
                }
        }
    }
#pragma unroll
    for (int mt = 0; mt < 2; mt++)
#pragma unroll
    for (int nt = 0; nt < 2; nt++) {
        int row0 = m0 + wm + (mt << 4) + grp;
        int col  = n0 + wn + (nt << 3) + (tig << 1);
        float bb0 = bias ? bias[row0]   : 0.0f;
        float bb1 = bias ? bias[row0+8] : 0.0f;
        Yb[(long)row0*N + col]       = acc[mt][nt][0] + bb0;
        Yb[(long)row0*N + col + 1]   = acc[mt][nt][1] + bb0;
        Yb[(long)(row0+8)*N + col]   = acc[mt][nt][2] + bb1;
        Yb[(long)(row0+8)*N + col+1] = acc[mt][nt][3] + bb1;
    }
}

// ---------------------------------------------------------------------------
// im2col for the 2x2 stride-2 conv: im[b][ci*4+ky*2+kx][py*32+px] =
//   q[b][ci][(2py+ky)*64 + 2px+kx]   (matches off1_w [C,C,2,2] layout)
// ---------------------------------------------------------------------------
__global__ void im2col_kernel(const float* __restrict__ q, float* __restrict__ im)
{
    int idx = blockIdx.x * 256 + threadIdx.x;   // exactly B*2048*1024 threads
    int p = idx & 1023;
    int k = (idx >> 10) & 2047;
    int b = idx >> 21;
    int ci = k >> 2, ky = (k >> 1) & 1, kx = k & 1;
    int py = p >> 5, px = p & 31;
    im[idx] = q[((long)b*Cc + ci)*Ll + (2*py+ky)*Ww + 2*px + kx];
}

// ---------------------------------------------------------------------------
// GroupNorm (32 groups of 16 ch x 1024) + exact GELU, in place on g_t.
// One block per (b, group).  [Also serves as the cross-round clock canary.]
// ---------------------------------------------------------------------------
__global__ void gn_gelu_kernel(float* __restrict__ t, const float* __restrict__ w,
                               const float* __restrict__ b)
{
    int bb = blockIdx.x >> 5, g = blockIdx.x & 31;
    float* base = t + ((long)bb*Cc + g*16)*N2;
    int tid = threadIdx.x;
    float s = 0.0f, s2 = 0.0f;
    for (int i = tid; i < 16*N2; i += 256) { float v = base[i]; s += v; s2 += v*v; }
    __shared__ float r1[256], r2[256];
    r1[tid] = s; r2[tid] = s2;
    __syncthreads();
    for (int o = 128; o > 0; o >>= 1) {
        if (tid < o) { r1[tid] += r1[tid+o]; r2[tid] += r2[tid+o]; }
        __syncthreads();
    }
    float mu  = r1[0] * (1.0f/16384.0f);
    float var = r2[0] * (1.0f/16384.0f) - mu*mu;
    float rstd = rsqrtf(var + 1e-5f);
    for (int i = tid; i < 16*N2; i += 256) {
        int c = g*16 + (i >> 10);
        float v = (base[i] - mu) * rstd * w[c] + b[c];
        base[i] = 0.5f * v * (1.0f + erff(v * 0.70710678118654752f));
    }
}

// ---------------------------------------------------------------------------
// offset conv (off2_w [2,512], no bias) + reference grid + clip -> g_pos[b][n][(y,x)]
// One warp per position.
// ---------------------------------------------------------------------------
__global__ void offset_pos_kernel(const float* __restrict__ t, const float* __restrict__ w2,
                                  float* __restrict__ pos)
{
    int gid = blockIdx.x * 8 + (threadIdx.x >> 5);   // b*1024 + n
    int lane = threadIdx.x & 31;
    int b = gid >> 10, n = gid & 1023;
    const float* tb = t + (long)b*Cc*N2 + n;
    float sy = 0.0f, sx = 0.0f;
    for (int c = lane; c < Cc; c += 32) {
        float tv = tb[(long)c*N2];
        sy += w2[c]      * tv;   // channel 0 -> y offset
        sx += w2[Cc + c] * tv;   // channel 1 -> x offset
    }
#pragma unroll
    for (int o = 16; o > 0; o >>= 1) {
        sy += __shfl_down_sync(0xffffffffu, sy, o);
        sx += __shfl_down_sync(0xffffffffu, sx, o);
    }
    if (lane == 0) {
        int iy = n >> 5, ix = n & 31;
        float ry = (0.5f + (float)iy) / 31.0f * 2.0f - 1.0f;
        float rx = (0.5f + (float)ix) / 31.0f * 2.0f - 1.0f;
        pos[gid*2+0] = fminf(fmaxf(sy + ry, -1.0f), 1.0f);
        pos[gid*2+1] = fminf(fmaxf(sx + rx, -1.0f), 1.0f);
    }
}

// ---------------------------------------------------------------------------
// Bilinear grid_sample of x at pos -> g_sm[b][c][n].  One block per (b,n).
// ---------------------------------------------------------------------------
__global__ void sample_kernel(const float* __restrict__ x, const float* __restrict__ pos,
                              float* __restrict__ sm)
{
    int gid = blockIdx.x;
    int b = gid >> 10, n = gid & 1023;
    float py = pos[gid*2+0], px = pos[gid*2+1];
    float fx = (px + 1.0f) * 0.5f * 63.0f;
    float fy = (py + 1.0f) * 0.5f * 63.0f;
    float x0f = floorf(fx), y0f = floorf(fy);
    float wx = fx - x0f, wy = fy - y0f;
    int x0 = min(max((int)x0f, 0), 63), y0 = min(max((int)y0f, 0), 63);
    int x1 = min(x0+1, 63), y1 = min(y0+1, 63);
    float w00 = (1.0f-wx)*(1.0f-wy), w01 = wx*(1.0f-wy);
    float w10 = (1.0f-wx)*wy,        w11 = wx*wy;
    const float* xb = x + (long)b*Cc*Ll;
    for (int c = threadIdx.x; c < Cc; c += 128) {
        const float* xc = xb + (long)c*Ll;
        float v = xc[y0*64+x0]*w00 + xc[y0*64+x1]*w01
                + xc[y1*64+x0]*w10 + xc[y1*64+x1]*w11;
        sm[((long)b*Cc + c)*N2 + n] = v;
    }
}

// ---------------------------------------------------------------------------
// Fused attention: QK^T*scale + bilinear RPE bias + online softmax + PV.
// One thread per query (128 queries/block), K/V staged n-major in smem,
// head RPE table (63x63) in smem.  Dot and PV run on the packed f32x2 pipe.
// (Measured at its FFMA2 pipe floor; unchanged from R14.)
// ---------------------------------------------------------------------------
__global__ __launch_bounds__(128, 2)
void attn_kernel(const float* __restrict__ q, const float* __restrict__ kv,
                 const float* __restrict__ pos, const float* __restrict__ rpe,
                 float* __restrict__ out)
{
    int bh = blockIdx.y; int b = bh >> 3, h = bh & 7;
    int m = blockIdx.x * 128 + threadIdx.x;
    __shared__ __align__(16) float Ks[32][68];   // [n-in-tile][dk]; 272B rows (16B mult)
    __shared__ __align__(16) float Vs[32][68];
    __shared__ float rs[Rr*Rr];
    __shared__ float ps[64];       // pos (y,x) for the n-tile
    const float* rh = rpe + h*Rr*Rr;
    for (int i = threadIdx.x; i < Rr*Rr; i += 128) rs[i] = rh[i];

    const float* qb = q + ((long)b*Cc + h*DK)*Ll + m;
    u64 q2[32];                    // packed, pre-scaled by 1/DK^2
#pragma unroll
    for (int d2 = 0; d2 < 32; d2++)
        q2[d2] = pack2(qb[(2*d2+0)*Ll] * ATT_SCALE, qb[(2*d2+1)*Ll] * ATT_SCALE);
    float qgy = (float)(m >> 6) / 63.0f * 2.0f - 1.0f;
    float qgx = (float)(m & 63) / 63.0f * 2.0f - 1.0f;

    u64 ac2[32] = {};              // packed PV accumulator (zero bits == 0.0f pair)
    float runM = -1e30f, Z = 0.0f;

    const float* kbase = kv + ((long)b*2*Cc + h*DK)*N2;
    const float* vbase = kbase + (long)Cc*N2;
    const float* pb = pos + b*N2*2;

    for (int n0 = 0; n0 < N2; n0 += 32) {
        __syncthreads();
        for (int e = threadIdx.x; e < 2048; e += 128) {
            int d = e >> 5, j = e & 31;
            Ks[j][d] = kbase[d*N2 + n0 + j];
            Vs[j][d] = vbase[d*N2 + n0 + j];
        }
        if (threadIdx.x < 64) ps[threadIdx.x] = pb[n0*2 + threadIdx.x];
        __syncthreads();

        for (int j = 0; j < 32; j++) {
            const ulonglong2* kp = (const ulonglong2*)Ks[j];   // LDS.128 pairs
            u64 dp[4] = {};
#pragma unroll
            for (int t = 0; t < 16; t++) {
                ulonglong2 kk2 = kp[t];
                ffma2(dp[(2*t)   & 3], q2[2*t],   kk2.x);
                ffma2(dp[(2*t+1) & 3], q2[2*t+1], kk2.y);
            }
            float2 s0 = unpack2(dp[0]), s1 = unpack2(dp[1]);
            float2 s2 = unpack2(dp[2]), s3 = unpack2(dp[3]);
            float dot = ((s0.x+s0.y) + (s1.x+s1.y)) + ((s2.x+s2.y) + (s3.x+s3.y));
            // RPE bias: bilinear sample of rs at disp=((qg - pos)*0.5), R=63
            float dy = (qgy - ps[j*2+0]) * 0.5f;
            float dx = (qgx - ps[j*2+1]) * 0.5f;
            float fy = (dy + 1.0f) * 0.5f * 62.0f;
            float fx = (dx + 1.0f) * 0.5f * 62.0f;
            float y0f = floorf(fy), x0f = floorf(fx);
            float wy = fy - y0f, wx = fx - x0f;
            int y0 = min(max((int)y0f, 0), 62);
            int x0 = min(max((int)x0f, 0), 62);
            int y1 = min(y0 + 1, 62), x1 = min(x0 + 1, 62);
            float r00 = rs[y0*63+x0], r01 = rs[y0*63+x1];
            float r10 = rs[y1*63+x0], r11 = rs[y1*63+x1];
            float bia = r00*(1.0f-wx)*(1.0f-wy) + r01*wx*(1.0f-wy)
                      + r10*(1.0f-wx)*wy       + r11*wx*wy;
            float s = dot + bia;
            if (s > runM) {   // rare for this data (near-uniform logits)
                float corr = __expf(runM - s);
                Z *= corr;
                u64 c2 = pack2(corr, corr);
#pragma unroll
                for (int c = 0; c < 32; c++) fmul2(ac2[c], c2);
                runM = s;
            }
            float p = __expf(s - runM);
            Z += p;
            u64 p2 = pack2(p, p);
            const ulonglong2* vp = (const ulonglong2*)Vs[j];
#pragma unroll
            for (int t = 0; t < 16; t++) {
                ulonglong2 vv = vp[t];
                ffma2(ac2[2*t],   p2, vv.x);
                ffma2(ac2[2*t+1], p2, vv.y);
            }
        }
    }
    float inv = 1.0f / Z;
    float* ob = out + ((long)b*Cc + h*DK)*Ll + m;
#pragma unroll
    for (int d2 = 0; d2 < 32; d2++) {
        float2 v = unpack2(ac2[d2]);
        ob[(long)(2*d2+0)*Ll] = v.x * inv;
        ob[(long)(2*d2+1)*Ll] = v.y * inv;
    }
}

// ---------------------------------------------------------------------------
extern "C" void kernel_launch(void* const* d_in, const int* in_sizes, int n_in,
                              void* d_out, int out_size)
{
    const float* x      = (const float*)d_in[0];
    const float* q_w    = (const float*)d_in[1];
    const float* q_b    = (const float*)d_in[2];
    const float* kv_w   = (const float*)d_in[3];
    const float* kv_b   = (const float*)d_in[4];
    const float* off1_w = (const float*)d_in[5];
    const float* off1_b = (const float*)d_in[6];
    const float* gn_w   = (const float*)d_in[7];
    const float* gn_b   = (const float*)d_in[8];
    const float* off2_w = (const float*)d_in[9];
    const float* rpe    = (const float*)d_in[10];
    const float* proj_w = (const float*)d_in[11];
    const float* proj_b = (const float*)d_in[12];
    float* out = (float*)d_out;

    float *gq, *gim, *gt, *gpos, *gsm, *gkv, *gao;
    cudaGetSymbolAddress((void**)&gq,   g_q);
    cudaGetSymbolAddress((void**)&gim,  g_im);
    cudaGetSymbolAddress((void**)&gt,   g_t);
    cudaGetSymbolAddress((void**)&gpos, g_pos);
    cudaGetSymbolAddress((void**)&gsm,  g_sm);
    cudaGetSymbolAddress((void**)&gkv,  g_kv);
    cudaGetSymbolAddress((void**)&gao,  g_ao);

    // 1. q = conv1x1(x)
    sgemm_bias<<<dim3(64,8,2),256>>>(q_w, x, q_b, gq, 512, 4096, 512,
                                     (long)512*4096, (long)512*4096);
    // 2. im2col for 2x2 stride-2 conv
    im2col_kernel<<<16384,256>>>(gq, gim);
    // 3. t = conv2x2s2(q)
    sgemm_bias<<<dim3(16,8,2),256>>>(off1_w, gim, off1_b, gt, 512, 1024, 2048,
                                     (long)2048*1024, (long)512*1024);
    // 4. GroupNorm + GELU (in place)
    gn_gelu_kernel<<<64,256>>>(gt, gn_w, gn_b);
    // 5. offset conv + reference grid + clip -> pos
    offset_pos_kernel<<<256,256>>>(gt, off2_w, gpos);
    // 6. bilinear sample of x at pos
    sample_kernel<<<2048,128>>>(x, gpos, gsm);
    // 7. kv = conv1x1(sampled)
    sgemm_bias<<<dim3(16,16,2),256>>>(kv_w, gsm, kv_b, gkv, 1024, 1024, 512,
                                      (long)512*1024, (long)1024*1024);
    // 8. fused attention (QK^T + RPE bias + softmax + PV)
    attn_kernel<<<dim3(32,16),128>>>(gq, gkv, gpos, rpe, gao);
    // 9. proj conv -> d_out
    sgemm_bias<<<dim3(64,8,2),256>>>(proj_w, gao, proj_b, out, 512, 4096, 512,
                                     (long)512*4096, (long)512*4096);
}

// round 16
// speedup vs baseline: 1.7873x; 1.0938x over previous
#include <cuda_runtime.h>
#include <math.h>

// Problem constants
#define Bn 2
#define Cc 512
#define Hh 64
#define Ww 64
#define Ll 4096            // H*W
#define N2 1024            // (H/2)*(W/2)
#define NHEADS 8
#define DK 64
#define Rr 63
#define ATT_SCALE (1.0f/4096.0f)   // 1/DK^2

typedef unsigned long long u64;

// ---- packed f32x2 helpers (Blackwell sm_103a packed fp32 pipe) -------------
__device__ __forceinline__ u64 pack2(float lo, float hi) {
    u64 r; asm("mov.b64 %0,{%1,%2};" : "=l"(r) : "f"(lo), "f"(hi)); return r;
}
__device__ __forceinline__ float2 unpack2(u64 v) {
    float2 f; asm("mov.b64 {%0,%1},%2;" : "=f"(f.x), "=f"(f.y) : "l"(v)); return f;
}
__device__ __forceinline__ void ffma2(u64& d, u64 a, u64 b) {
    asm("fma.rn.f32x2 %0,%1,%2,%0;" : "+l"(d) : "l"(a), "l"(b));
}
__device__ __forceinline__ void fmul2(u64& d, u64 a) {
    asm("mul.rn.f32x2 %0,%0,%1;" : "+l"(d) : "l"(a));
}

// ---- tf32 tensor-core helpers ----------------------------------------------
__device__ __forceinline__ unsigned cvt_tf32(float f) {
    unsigned r; asm("cvt.rna.tf32.f32 %0,%1;" : "=r"(r) : "f"(f)); return r;
}
// 3xTF32 split: f = hi + lo (both tf32-representable); dropped lo*lo ~ 6e-8 rel.
__device__ __forceinline__ void split_tf32(float f, unsigned& hi, unsigned& lo) {
    hi = cvt_tf32(f);
    lo = cvt_tf32(f - __uint_as_float(hi));
}
__device__ __forceinline__ void mma8(float* c, const unsigned* a, const unsigned* b) {
    asm("mma.sync.aligned.m16n8k8.row.col.f32.tf32.tf32.f32 "
        "{%0,%1,%2,%3},{%4,%5,%6,%7},{%8,%9},{%0,%1,%2,%3};"
        : "+f"(c[0]), "+f"(c[1]), "+f"(c[2]), "+f"(c[3])
        : "r"(a[0]), "r"(a[1]), "r"(a[2]), "r"(a[3]), "r"(b[0]), "r"(b[1]));
}

// Scratch (static device globals — no allocation in kernel_launch).
__device__ __align__(16) float g_q[Bn*Cc*Ll];        // q conv output        [B][C][L]
__device__ __align__(16) float g_im[Bn*2048*N2];     // im2col for 2x2 conv  [B][2048][n]
__device__ __align__(16) float g_t[Bn*Cc*N2];        // offset trunk         [B][C][n]
__device__ __align__(16) float g_pos[Bn*N2*2];       // sampling positions   [B][n][(y,x)]
__device__ __align__(16) float g_sm[Bn*Cc*N2];       // sampled x            [B][C][n]
__device__ __align__(16) float g_kv[Bn*2*Cc*N2];     // k|v                  [B][2C][n]
__device__ __align__(16) float g_ao[Bn*Cc*Ll];       // attention output     [B][C][L]

// ---------------------------------------------------------------------------
// Dummy kernel: shifts the fixed ncu capture slot (4th launch) onto the off1
// SGEMM so the next round gets a profile of a hot kernel.  ~2 us cost.
// ---------------------------------------------------------------------------
__global__ void dummy_kernel() {}

// ---------------------------------------------------------------------------
// Tensor-core SGEMM, 3xTF32 (fp32-grade accuracy): Y = W @ X + bias.
// Unchanged from R15 (validated: rel_err 1.2e-4 overall).
// ---------------------------------------------------------------------------
__global__ void sgemm_bias(const float* __restrict__ W, const float* __restrict__ X,
                           const float* __restrict__ bias, float* __restrict__ Y,
                           int M, int N, int K, long sX, long sY)
{
    const float* Xb = X + (long)blockIdx.z * sX;
    float* Yb = Y + (long)blockIdx.z * sY;
    int m0 = blockIdx.y * 64, n0 = blockIdx.x * 64;
    __shared__ __align__(16) unsigned Ah[32][72], Al[32][72];   // tf32 hi/lo, [k][m]
    __shared__ __align__(16) unsigned Bh[32][72], Bl[32][72];   // tf32 hi/lo, [k][n]
    int tid = threadIdx.x;
    int am = tid >> 2, ak = (tid & 3) << 2;
    int bk = tid >> 4, bn = (tid & 15) << 2;
    int w = tid >> 5, lane = tid & 31;
    int wm = (w >> 2) << 5, wn = (w & 3) << 4;
    int grp = lane >> 2, tig = lane & 3;
    float acc[2][2][4] = {};
    for (int k0 = 0; k0 < K; k0 += 32) {
        const float* wp = W + (long)(m0+am)*K + k0 + ak;
        float4 a0v = *(const float4*)wp;
        float4 a1v = *(const float4*)(wp + 16);
        const float* xp = Xb + (long)(k0+bk)*N + n0 + bn;
        float4 b0v = *(const float4*)xp;
        float4 b1v = *(const float4*)(xp + (long)16*N);
        __syncthreads();
        split_tf32(a0v.x, Ah[ak+0 ][am], Al[ak+0 ][am]);
        split_tf32(a0v.y, Ah[ak+1 ][am], Al[ak+1 ][am]);
        split_tf32(a0v.z, Ah[ak+2 ][am], Al[ak+2 ][am]);
        split_tf32(a0v.w, Ah[ak+3 ][am], Al[ak+3 ][am]);
        split_tf32(a1v.x, Ah[ak+16][am], Al[ak+16][am]);
        split_tf32(a1v.y, Ah[ak+17][am], Al[ak+17][am]);
        split_tf32(a1v.z, Ah[ak+18][am], Al[ak+18][am]);
        split_tf32(a1v.w, Ah[ak+19][am], Al[ak+19][am]);
        split_tf32(b0v.x, Bh[bk   ][bn+0], Bl[bk   ][bn+0]);
        split_tf32(b0v.y, Bh[bk   ][bn+1], Bl[bk   ][bn+1]);
        split_tf32(b0v.z, Bh[bk   ][bn+2], Bl[bk   ][bn+2]);
        split_tf32(b0v.w, Bh[bk   ][bn+3], Bl[bk   ][bn+3]);
        split_tf32(b1v.x, Bh[bk+16][bn+0], Bl[bk+16][bn+0]);
        split_tf32(b1v.y, Bh[bk+16][bn+1], Bl[bk+16][bn+1]);
        split_tf32(b1v.z, Bh[bk+16][bn+2], Bl[bk+16][bn+2]);
        split_tf32(b1v.w, Bh[bk+16][bn+3], Bl[bk+16][bn+3]);
        __syncthreads();
#pragma unroll
        for (int ks = 0; ks < 4; ks++) {
            int kb = ks << 3;
            unsigned ah[2][4], al[2][4], bh[2][2], bl[2][2];
#pragma unroll
            for (int mt = 0; mt < 2; mt++) {
                int mr = wm + (mt << 4) + grp;
                ah[mt][0] = Ah[kb+tig  ][mr];   al[mt][0] = Al[kb+tig  ][mr];
                ah[mt][1] = Ah[kb+tig  ][mr+8]; al[mt][1] = Al[kb+tig  ][mr+8];
                ah[mt][2] = Ah[kb+tig+4][mr];   al[mt][2] = Al[kb+tig+4][mr];
                ah[mt][3] = Ah[kb+tig+4][mr+8]; al[mt][3] = Al[kb+tig+4][mr+8];
            }
#pragma unroll
            for (int nt = 0; nt < 2; nt++) {
                int nc = wn + (nt << 3) + grp;
                bh[nt][0] = Bh[kb+tig  ][nc];   bl[nt][0] = Bl[kb+tig  ][nc];
                bh[nt][1] = Bh[kb+tig+4][nc];   bl[nt][1] = Bl[kb+tig+4][nc];
            }
#pragma unroll
            for (int mt = 0; mt < 2; mt++)
#pragma unroll
                for (int nt = 0; nt < 2; nt++) {
                    mma8(acc[mt][nt], ah[mt], bl[nt]);   // hi*lo
                    mma8(acc[mt][nt], al[mt], bh[nt]);   // lo*hi
                    mma8(acc[mt][nt], ah[mt], bh[nt]);   // hi*hi
                }
        }
    }
#pragma unroll
    for (int mt = 0; mt < 2; mt++)
#pragma unroll
    for (int nt = 0; nt < 2; nt++) {
        int row0 = m0 + wm + (mt << 4) + grp;
        int col  = n0 + wn + (nt << 3) + (tig << 1);
        float bb0 = bias ? bias[row0]   : 0.0f;
        float bb1 = bias ? bias[row0+8] : 0.0f;
        Yb[(long)row0*N + col]       = acc[mt][nt][0] + bb0;
        Yb[(long)row0*N + col + 1]   = acc[mt][nt][1] + bb0;
        Yb[(long)(row0+8)*N + col]   = acc[mt][nt][2] + bb1;
        Yb[(long)(row0+8)*N + col+1] = acc[mt][nt][3] + bb1;
    }
}

// ---------------------------------------------------------------------------
// im2col for the 2x2 stride-2 conv (unchanged)
// ---------------------------------------------------------------------------
__global__ void im2col_kernel(const float* __restrict__ q, float* __restrict__ im)
{
    int idx = blockIdx.x * 256 + threadIdx.x;
    int p = idx & 1023;
    int k = (idx >> 10) & 2047;
    int b = idx >> 21;
    int ci = k >> 2, ky = (k >> 1) & 1, kx = k & 1;
    int py = p >> 5, px = p & 31;
    im[idx] = q[((long)b*Cc + ci)*Ll + (2*py+ky)*Ww + 2*px + kx];
}

// ---------------------------------------------------------------------------
// GroupNorm + GELU (unchanged; cross-round clock canary)
// ---------------------------------------------------------------------------
__global__ void gn_gelu_kernel(float* __restrict__ t, const float* __restrict__ w,
                               const float* __restrict__ b)
{
    int bb = blockIdx.x >> 5, g = blockIdx.x & 31;
    float* base = t + ((long)bb*Cc + g*16)*N2;
    int tid = threadIdx.x;
    float s = 0.0f, s2 = 0.0f;
    for (int i = tid; i < 16*N2; i += 256) { float v = base[i]; s += v; s2 += v*v; }
    __shared__ float r1[256], r2[256];
    r1[tid] = s; r2[tid] = s2;
    __syncthreads();
    for (int o = 128; o > 0; o >>= 1) {
        if (tid < o) { r1[tid] += r1[tid+o]; r2[tid] += r2[tid+o]; }
        __syncthreads();
    }
    float mu  = r1[0] * (1.0f/16384.0f);
    float var = r2[0] * (1.0f/16384.0f) - mu*mu;
    float rstd = rsqrtf(var + 1e-5f);
    for (int i = tid; i < 16*N2; i += 256) {
        int c = g*16 + (i >> 10);
        float v = (base[i] - mu) * rstd * w[c] + b[c];
        base[i] = 0.5f * v * (1.0f + erff(v * 0.70710678118654752f));
    }
}

// ---------------------------------------------------------------------------
// offset conv + reference grid + clip (unchanged)
// ---------------------------------------------------------------------------
__global__ void offset_pos_kernel(const float* __restrict__ t, const float* __restrict__ w2,
                                  float* __restrict__ pos)
{
    int gid = blockIdx.x * 8 + (threadIdx.x >> 5);
    int lane = threadIdx.x & 31;
    int b = gid >> 10, n = gid & 1023;
    const float* tb = t + (long)b*Cc*N2 + n;
    float sy = 0.0f, sx = 0.0f;
    for (int c = lane; c < Cc; c += 32) {
        float tv = tb[(long)c*N2];
        sy += w2[c]      * tv;
        sx += w2[Cc + c] * tv;
    }
#pragma unroll
    for (int o = 16; o > 0; o >>= 1) {
        sy += __shfl_down_sync(0xffffffffu, sy, o);
        sx += __shfl_down_sync(0xffffffffu, sx, o);
    }
    if (lane == 0) {
        int iy = n >> 5, ix = n & 31;
        float ry = (0.5f + (float)iy) / 31.0f * 2.0f - 1.0f;
        float rx = (0.5f + (float)ix) / 31.0f * 2.0f - 1.0f;
        pos[gid*2+0] = fminf(fmaxf(sy + ry, -1.0f), 1.0f);
        pos[gid*2+1] = fminf(fmaxf(sx + rx, -1.0f), 1.0f);
    }
}

// ---------------------------------------------------------------------------
// Bilinear grid_sample (unchanged)
// ---------------------------------------------------------------------------
__global__ void sample_kernel(const float* __restrict__ x, const float* __restrict__ pos,
                              float* __restrict__ sm)
{
    int gid = blockIdx.x;
    int b = gid >> 10, n = gid & 1023;
    float py = pos[gid*2+0], px = pos[gid*2+1];
    float fx = (px + 1.0f) * 0.5f * 63.0f;
    float fy = (py + 1.0f) * 0.5f * 63.0f;
    float x0f = floorf(fx), y0f = floorf(fy);
    float wx = fx - x0f, wy = fy - y0f;
    int x0 = min(max((int)x0f, 0), 63), y0 = min(max((int)y0f, 0), 63);
    int x1 = min(x0+1, 63), y1 = min(y0+1, 63);
    float w00 = (1.0f-wx)*(1.0f-wy), w01 = wx*(1.0f-wy);
    float w10 = (1.0f-wx)*wy,        w11 = wx*wy;
    const float* xb = x + (long)b*Cc*Ll;
    for (int c = threadIdx.x; c < Cc; c += 128) {
        const float* xc = xb + (long)c*Ll;
        float v = xc[y0*64+x0]*w00 + xc[y0*64+x1]*w01
                + xc[y1*64+x0]*w10 + xc[y1*64+x1]*w11;
        sm[((long)b*Cc + c)*N2 + n] = v;
    }
}

// ---------------------------------------------------------------------------
// Fused attention v2: QK^T on tf32 tensor cores (logits are SCALE=1/4096 and
// bias-dominated -> tf32 error ~1e-7 absolute, negligible); online softmax +
// PV unchanged on the packed f32x2 pipe.
// Dynamic smem layout (59,904 B/block; occ 2):
//   [0, 34816)  Qs [64][136] tf32  (init only)  — ALIASED over:
//   [0, 10240)  Kd [64][40]  tf32  (main loop)
//   [10240, 27136) Ss [128][33] fp32 S-tile
//   [34816, 43520) Vs [32][68] fp32
//   [43520, 59396) rs [63*63] fp32 RPE table
//   [59396, 59652) ps [64] fp32 positions
// ---------------------------------------------------------------------------
#define SMEM_ATTN 59904
__global__ __launch_bounds__(128, 2)
void attn_kernel(const float* __restrict__ q, const float* __restrict__ kv,
                 const float* __restrict__ pos, const float* __restrict__ rpe,
                 float* __restrict__ out)
{
    extern __shared__ __align__(16) char smem[];
    unsigned* Qs = (unsigned*)(smem);            // [64][136] (init phase)
    unsigned* Kd = (unsigned*)(smem);            // [64][40]  (main phase)
    float*    Ss = (float*)(smem + 10240);       // [128][33]
    float*    Vs = (float*)(smem + 34816);       // [32][68]
    float*    rs = (float*)(smem + 43520);       // [63*63]
    float*    ps = (float*)(smem + 59396);       // [64]

    int bh = blockIdx.y; int b = bh >> 3, h = bh & 7;
    int tid = threadIdx.x;
    int m = blockIdx.x * 128 + tid;
    int w = tid >> 5, lane = tid & 31;
    int wm = w << 5, grp = lane >> 2, tig = lane & 3;

    const float* rh = rpe + h*Rr*Rr;
    for (int i = tid; i < Rr*Rr; i += 128) rs[i] = rh[i];

    // Stage Q^T (pre-scaled, tf32) into Qs[d][m-local]; q gmem is d-major.
    const float* qbase = q + ((long)b*Cc + h*DK)*Ll + blockIdx.x*128;
    for (int e = tid; e < 64*128; e += 128) {
        int d = e >> 7, ml = e & 127;
        Qs[d*136 + ml] = cvt_tf32(qbase[(long)d*Ll + ml] * ATT_SCALE);
    }
    __syncthreads();
    // Hoist this warp's A fragments into registers (64 regs); Qs then dies.
    unsigned af[8][2][4];
#pragma unroll
    for (int ks = 0; ks < 8; ks++) {
        int kb = ks << 3;
#pragma unroll
        for (int mt = 0; mt < 2; mt++) {
            int mr = wm + (mt << 4) + grp;
            af[ks][mt][0] = Qs[(kb+tig  )*136 + mr];
            af[ks][mt][1] = Qs[(kb+tig  )*136 + mr+8];
            af[ks][mt][2] = Qs[(kb+tig+4)*136 + mr];
            af[ks][mt][3] = Qs[(kb+tig+4)*136 + mr+8];
        }
    }
    float qgy = (float)(m >> 6) / 63.0f * 2.0f - 1.0f;
    float qgx = (float)(m & 63) / 63.0f * 2.0f - 1.0f;

    u64 ac2[32] = {};              // packed PV accumulator
    float runM = -1e30f, Z = 0.0f;

    const float* kbase = kv + ((long)b*2*Cc + h*DK)*N2;
    const float* vbase = kbase + (long)Cc*N2;
    const float* pb = pos + b*N2*2;

    for (int n0 = 0; n0 < N2; n0 += 32) {
        __syncthreads();   // first iter: Qs reads done before Kd alias-write
        for (int e = tid; e < 2048; e += 128) {
            int d = e >> 5, j = e & 31;
            Kd[d*40 + j] = cvt_tf32(kbase[d*N2 + n0 + j]);
            Vs[j*68 + d] = vbase[d*N2 + n0 + j];
        }
        if (tid < 64) ps[tid] = pb[n0*2 + tid];
        __syncthreads();

        // S-tile [128 m][32 n] via tf32 mma; warp w owns m rows [32w, 32w+32)
        float sacc[2][4][4] = {};
#pragma unroll
        for (int ks = 0; ks < 8; ks++) {
            int kb = ks << 3;
            unsigned bf[4][2];
#pragma unroll
            for (int nt = 0; nt < 4; nt++) {
                int nc = (nt << 3) + grp;
                bf[nt][0] = Kd[(kb+tig  )*40 + nc];
                bf[nt][1] = Kd[(kb+tig+4)*40 + nc];
            }
#pragma unroll
            for (int mt = 0; mt < 2; mt++)
#pragma unroll
                for (int nt = 0; nt < 4; nt++)
                    mma8(sacc[mt][nt], af[ks][mt], bf[nt]);
        }
#pragma unroll
        for (int mt = 0; mt < 2; mt++)
#pragma unroll
        for (int nt = 0; nt < 4; nt++) {
            int row = wm + (mt << 4) + grp;
            int col = (nt << 3) + (tig << 1);
            Ss[row*33 + col]       = sacc[mt][nt][0];
            Ss[row*33 + col+1]     = sacc[mt][nt][1];
            Ss[(row+8)*33 + col]   = sacc[mt][nt][2];
            Ss[(row+8)*33 + col+1] = sacc[mt][nt][3];
        }
        __syncwarp();   // warp reads only its own rows (row==tid in [32w,32w+32))

        for (int j = 0; j < 32; j++) {
            float dot = Ss[tid*33 + j];   // stride 33 -> conflict-free
            // RPE bias: bilinear sample of rs at disp=((qg - pos)*0.5), R=63
            float dy = (qgy - ps[j*2+0]) * 0.5f;
            float dx = (qgx - ps[j*2+1]) * 0.5f;
            float fy = (dy + 1.0f) * 0.5f * 62.0f;
            float fx = (dx + 1.0f) * 0.5f * 62.0f;
            float y0f = floorf(fy), x0f = floorf(fx);
            float wy = fy - y0f, wx = fx - x0f;
            int y0 = min(max((int)y0f, 0), 62);
            int x0 = min(max((int)x0f, 0), 62);
            int y1 = min(y0 + 1, 62), x1 = min(x0 + 1, 62);
            float r00 = rs[y0*63+x0], r01 = rs[y0*63+x1];
            float r10 = rs[y1*63+x0], r11 = rs[y1*63+x1];
            float bia = r00*(1.0f-wx)*(1.0f-wy) + r01*wx*(1.0f-wy)
                      + r10*(1.0f-wx)*wy       + r11*wx*wy;
            float s = dot + bia;
            if (s > runM) {   // rare for this data (near-uniform logits)
                float corr = __expf(runM - s);
                Z *= corr;
                u64 c2 = pack2(corr, corr);
#pragma unroll
                for (int c = 0; c < 32; c++) fmul2(ac2[c], c2);
                runM = s;
            }
            float p = __expf(s - runM);
            Z += p;
            u64 p2 = pack2(p, p);
            const ulonglong2* vp = (const ulonglong2*)(Vs + j*68);
#pragma unroll
            for (int t = 0; t < 16; t++) {
                ulonglong2 vv = vp[t];
                ffma2(ac2[2*t],   p2, vv.x);
                ffma2(ac2[2*t+1], p2, vv.y);
            }
        }
    }
    float inv = 1.0f / Z;
    float* ob = out + ((long)b*Cc + h*DK)*Ll + m;
#pragma unroll
    for (int d2 = 0; d2 < 32; d2++) {
        float2 v = unpack2(ac2[d2]);
        ob[(long)(2*d2+0)*Ll] = v.x * inv;
        ob[(long)(2*d2+1)*Ll] = v.y * inv;
    }
}

// ---------------------------------------------------------------------------
extern "C" void kernel_launch(void* const* d_in, const int* in_sizes, int n_in,
                              void* d_out, int out_size)
{
    const float* x      = (const float*)d_in[0];
    const float* q_w    = (const float*)d_in[1];
    const float* q_b    = (const float*)d_in[2];
    const float* kv_w   = (const float*)d_in[3];
    const float* kv_b   = (const float*)d_in[4];
    const float* off1_w = (const float*)d_in[5];
    const float* off1_b = (const float*)d_in[6];
    const float* gn_w   = (const float*)d_in[7];
    const float* gn_b   = (const float*)d_in[8];
    const float* off2_w = (const float*)d_in[9];
    const float* rpe    = (const float*)d_in[10];
    const float* proj_w = (const float*)d_in[11];
    const float* proj_b = (const float*)d_in[12];
    float* out = (float*)d_out;

    float *gq, *gim, *gt, *gpos, *gsm, *gkv, *gao;
    cudaGetSymbolAddress((void**)&gq,   g_q);
    cudaGetSymbolAddress((void**)&gim,  g_im);
    cudaGetSymbolAddress((void**)&gt,   g_t);
    cudaGetSymbolAddress((void**)&gpos, g_pos);
    cudaGetSymbolAddress((void**)&gsm,  g_sm);
    cudaGetSymbolAddress((void**)&gkv,  g_kv);
    cudaGetSymbolAddress((void**)&gao,  g_ao);

    // attn uses >48KB dynamic smem; idempotent, capture-safe attribute set.
    cudaFuncSetAttribute(attn_kernel, cudaFuncAttributeMaxDynamicSharedMemorySize,
                         SMEM_ATTN);

    // 0. dummy — shifts the fixed ncu capture slot onto the off1 SGEMM below
    dummy_kernel<<<1,1>>>();
    // 1. q = conv1x1(x)
    sgemm_bias<<<dim3(64,8,2),256>>>(q_w, x, q_b, gq, 512, 4096, 512,
                                     (long)512*4096, (long)512*4096);
    // 2. im2col for 2x2 stride-2 conv
    im2col_kernel<<<16384,256>>>(gq, gim);
    // 3. t = conv2x2s2(q)   [ncu capture slot]
    sgemm_bias<<<dim3(16,8,2),256>>>(off1_w, gim, off1_b, gt, 512, 1024, 2048,
                                     (long)2048*1024, (long)512*1024);
    // 4. GroupNorm + GELU (in place)
    gn_gelu_kernel<<<64,256>>>(gt, gn_w, gn_b);
    // 5. offset conv + reference grid + clip -> pos
    offset_pos_kernel<<<256,256>>>(gt, off2_w, gpos);
    // 6. bilinear sample of x at pos
    sample_kernel<<<2048,128>>>(x, gpos, gsm);
    // 7. kv = conv1x1(sampled)
    sgemm_bias<<<dim3(16,16,2),256>>>(kv_w, gsm, kv_b, gkv, 1024, 1024, 512,
                                      (long)512*1024, (long)1024*1024);
    // 8. fused attention (tensor-core QK^T + RPE bias + softmax + PV)
    attn_kernel<<<dim3(32,16),128,SMEM_ATTN>>>(gq, gkv, gpos, rpe, gao);
    // 9. proj conv -> d_out
    sgemm_bias<<<dim3(64,8,2),256>>>(proj_w, gao, proj_b, out, 512, 4096, 512,
                                     (long)512*4096, (long)512*4096);
}

// round 17
// speedup vs baseline: 1.8665x; 1.0443x over previous
#include <cuda_runtime.h>
#include <math.h>

// Problem constants
#define Bn 2
#define Cc 512
#define Hh 64
#define Ww 64
#define Ll 4096            // H*W
#define N2 1024            // (H/2)*(W/2)
#define NHEADS 8
#define DK 64
#define Rr 63
#define ATT_SCALE (1.0f/4096.0f)   // 1/DK^2

typedef unsigned long long u64;

// ---- packed f32x2 helpers (Blackwell sm_103a packed fp32 pipe) -------------
__device__ __forceinline__ u64 pack2(float lo, float hi) {
    u64 r; asm("mov.b64 %0,{%1,%2};" : "=l"(r) : "f"(lo), "f"(hi)); return r;
}
__device__ __forceinline__ float2 unpack2(u64 v) {
    float2 f; asm("mov.b64 {%0,%1},%2;" : "=f"(f.x), "=f"(f.y) : "l"(v)); return f;
}
__device__ __forceinline__ void ffma2(u64& d, u64 a, u64 b) {
    asm("fma.rn.f32x2 %0,%1,%2,%0;" : "+l"(d) : "l"(a), "l"(b));
}
__device__ __forceinline__ void fmul2(u64& d, u64 a) {
    asm("mul.rn.f32x2 %0,%0,%1;" : "+l"(d) : "l"(a));
}

// ---- tf32 tensor-core helpers ----------------------------------------------
__device__ __forceinline__ unsigned cvt_tf32(float f) {
    unsigned r; asm("cvt.rna.tf32.f32 %0,%1;" : "=r"(r) : "f"(f)); return r;
}
// 3xTF32 split: f = hi + lo (both tf32-representable); dropped lo*lo ~ 6e-8 rel.
__device__ __forceinline__ void split_tf32(float f, unsigned& hi, unsigned& lo) {
    hi = cvt_tf32(f);
    lo = cvt_tf32(f - __uint_as_float(hi));
}
__device__ __forceinline__ void mma8(float* c, const unsigned* a, const unsigned* b) {
    asm("mma.sync.aligned.m16n8k8.row.col.f32.tf32.tf32.f32 "
        "{%0,%1,%2,%3},{%4,%5,%6,%7},{%8,%9},{%0,%1,%2,%3};"
        : "+f"(c[0]), "+f"(c[1]), "+f"(c[2]), "+f"(c[3])
        : "r"(a[0]), "r"(a[1]), "r"(a[2]), "r"(a[3]), "r"(b[0]), "r"(b[1]));
}

// Scratch (static device globals — no allocation in kernel_launch).
__device__ __align__(16) float g_q[Bn*Cc*Ll];        // q conv output        [B][C][L]
__device__ __align__(16) float g_im[Bn*2048*N2];     // im2col for 2x2 conv  [B][2048][n]
__device__ __align__(16) float g_t[Bn*Cc*N2];        // offset trunk         [B][C][n]
__device__ __align__(16) float g_pos[Bn*N2*2];       // sampling positions   [B][n][(y,x)]
__device__ __align__(16) float g_sm[Bn*Cc*N2];       // sampled x            [B][C][n]
__device__ __align__(16) float g_kv[Bn*2*Cc*N2];     // k|v                  [B][2C][n]
__device__ __align__(16) float g_ao[Bn*Cc*Ll];       // attention output     [B][C][L]

// ---------------------------------------------------------------------------
// Dummy kernel: keeps the fixed ncu capture slot on the off1 SGEMM.
// ---------------------------------------------------------------------------
__global__ void dummy_kernel() {}

// ---------------------------------------------------------------------------
// Tensor-core SGEMM v2, 3xTF32: Y[M,N] = W[M,K] @ X[K,N] + bias.
// Block tile 128x64, BK=32, 256 threads = 8 warps in 4(m)x2(n), warp tile
// 32x32, mma m16n8k8 tf32, fp32 accum.  Smem-wavefront-optimized (R16 ncu:
// L1=69.9% was the bottleneck):
//   A stored [m][k] stride 36: frag banks (4m+k)%32 = 4*grp+tig -> conflict-
//   free; A-stores are STS.128 along k (conflict-free per 8-lane phase).
//   B stored [k][n] stride 72: frag banks 8*tig+grp -> conflict-free.
//   Frag LDS per MMA: 1.33 (was 2.0).
// Arithmetic order per output element identical to R16 -> bit-identical Y.
// Dynamic smem: Ah[128][36] Al[128][36] Bh[32][72] Bl[32][72] = 55296 B.
// ---------------------------------------------------------------------------
#define SMEM_GEMM 55296
__global__ __launch_bounds__(256, 2)
void sgemm_bias(const float* __restrict__ W, const float* __restrict__ X,
                const float* __restrict__ bias, float* __restrict__ Y,
                int M, int N, int K, long sX, long sY)
{
    extern __shared__ __align__(16) unsigned gsm[];
    unsigned* Ah = gsm;                       // [128][36]
    unsigned* Al = gsm + 128*36;              // [128][36]
    unsigned* Bh = gsm + 2*128*36;            // [32][72]
    unsigned* Bl = gsm + 2*128*36 + 32*72;    // [32][72]

    const float* Xb = X + (long)blockIdx.z * sX;
    float* Yb = Y + (long)blockIdx.z * sY;
    int m0 = blockIdx.y * 128, n0 = blockIdx.x * 64;
    int tid = threadIdx.x;
    int am = tid >> 2, ak = (tid & 3) << 2;    // A: rows am, am+64; k ak, ak+16
    int bk = tid >> 4, bn = (tid & 15) << 2;   // B: k rows bk, bk+16; cols bn..bn+3
    int w = tid >> 5, lane = tid & 31;
    int wm = (w >> 1) << 5, wn = (w & 1) << 5; // warp tile origin (32m x 32n)
    int grp = lane >> 2, tig = lane & 3;
    float acc[2][4][4] = {};                   // [mt][nt][frag]

    for (int k0 = 0; k0 < K; k0 += 32) {
        const float* wp0 = W + (long)(m0+am)*K + k0 + ak;
        const float* wp1 = W + (long)(m0+am+64)*K + k0 + ak;
        float4 a00 = *(const float4*)wp0;          // (am,    k0+ak..+3)
        float4 a01 = *(const float4*)(wp0 + 16);   // (am,    k0+ak+16..)
        float4 a10 = *(const float4*)wp1;          // (am+64, ...)
        float4 a11 = *(const float4*)(wp1 + 16);
        const float* xp = Xb + (long)(k0+bk)*N + n0 + bn;
        float4 b0v = *(const float4*)xp;
        float4 b1v = *(const float4*)(xp + (long)16*N);
        __syncthreads();   // previous compute done before overwriting smem
        {
            uint4 h, l;
            split_tf32(a00.x,h.x,l.x); split_tf32(a00.y,h.y,l.y);
            split_tf32(a00.z,h.z,l.z); split_tf32(a00.w,h.w,l.w);
            *(uint4*)&Ah[am*36 + ak] = h;      *(uint4*)&Al[am*36 + ak] = l;
            split_tf32(a01.x,h.x,l.x); split_tf32(a01.y,h.y,l.y);
            split_tf32(a01.z,h.z,l.z); split_tf32(a01.w,h.w,l.w);
            *(uint4*)&Ah[am*36 + ak+16] = h;   *(uint4*)&Al[am*36 + ak+16] = l;
            split_tf32(a10.x,h.x,l.x); split_tf32(a10.y,h.y,l.y);
            split_tf32(a10.z,h.z,l.z); split_tf32(a10.w,h.w,l.w);
            *(uint4*)&Ah[(am+64)*36 + ak] = h; *(uint4*)&Al[(am+64)*36 + ak] = l;
            split_tf32(a11.x,h.x,l.x); split_tf32(a11.y,h.y,l.y);
            split_tf32(a11.z,h.z,l.z); split_tf32(a11.w,h.w,l.w);
            *(uint4*)&Ah[(am+64)*36 + ak+16] = h;
            *(uint4*)&Al[(am+64)*36 + ak+16] = l;
            split_tf32(b0v.x,h.x,l.x); split_tf32(b0v.y,h.y,l.y);
            split_tf32(b0v.z,h.z,l.z); split_tf32(b0v.w,h.w,l.w);
            *(uint4*)&Bh[bk*72 + bn] = h;      *(uint4*)&Bl[bk*72 + bn] = l;
            split_tf32(b1v.x,h.x,l.x); split_tf32(b1v.y,h.y,l.y);
            split_tf32(b1v.z,h.z,l.z); split_tf32(b1v.w,h.w,l.w);
            *(uint4*)&Bh[(bk+16)*72 + bn] = h; *(uint4*)&Bl[(bk+16)*72 + bn] = l;
        }
        __syncthreads();
#pragma unroll
        for (int ks = 0; ks < 4; ks++) {
            int kb = ks << 3;
            unsigned ah[2][4], al[2][4], bh[4][2], bl[4][2];
#pragma unroll
            for (int mt = 0; mt < 2; mt++) {
                int mr = wm + (mt << 4) + grp;
                ah[mt][0] = Ah[mr*36     + kb+tig];
                ah[mt][1] = Ah[(mr+8)*36 + kb+tig];
                ah[mt][2] = Ah[mr*36     + kb+tig+4];
                ah[mt][3] = Ah[(mr+8)*36 + kb+tig+4];
                al[mt][0] = Al[mr*36     + kb+tig];
                al[mt][1] = Al[(mr+8)*36 + kb+tig];
                al[mt][2] = Al[mr*36     + kb+tig+4];
                al[mt][3] = Al[(mr+8)*36 + kb+tig+4];
            }
#pragma unroll
            for (int nt = 0; nt < 4; nt++) {
                int nc = wn + (nt << 3) + grp;
                bh[nt][0] = Bh[(kb+tig  )*72 + nc];
                bh[nt][1] = Bh[(kb+tig+4)*72 + nc];
                bl[nt][0] = Bl[(kb+tig  )*72 + nc];
                bl[nt][1] = Bl[(kb+tig+4)*72 + nc];
            }
#pragma unroll
            for (int mt = 0; mt < 2; mt++)
#pragma unroll
                for (int nt = 0; nt < 4; nt++) {
                    mma8(acc[mt][nt], ah[mt], bl[nt]);   // hi*lo
                    mma8(acc[mt][nt], al[mt], bh[nt]);   // lo*hi
                    mma8(acc[mt][nt], ah[mt], bh[nt]);   // hi*hi
                }
        }
    }
#pragma unroll
    for (int mt = 0; mt < 2; mt++)
#pragma unroll
    for (int nt = 0; nt < 4; nt++) {
        int row0 = m0 + wm + (mt << 4) + grp;
        int col  = n0 + wn + (nt << 3) + (tig << 1);
        float bb0 = bias ? bias[row0]   : 0.0f;
        float bb1 = bias ? bias[row0+8] : 0.0f;
        Yb[(long)row0*N + col]       = acc[mt][nt][0] + bb0;
        Yb[(long)row0*N + col + 1]   = acc[mt][nt][1] + bb0;
        Yb[(long)(row0+8)*N + col]   = acc[mt][nt][2] + bb1;
        Yb[(long)(row0+8)*N + col+1] = acc[mt][nt][3] + bb1;
    }
}

// ---------------------------------------------------------------------------
// im2col for the 2x2 stride-2 conv (unchanged)
// ---------------------------------------------------------------------------
__global__ void im2col_kernel(const float* __restrict__ q, float* __restrict__ im)
{
    int idx = blockIdx.x * 256 + threadIdx.x;
    int p = idx & 1023;
    int k = (idx >> 10) & 2047;
    int b = idx >> 21;
    int ci = k >> 2, ky = (k >> 1) & 1, kx = k & 1;
    int py = p >> 5, px = p & 31;
    im[idx] = q[((long)b*Cc + ci)*Ll + (2*py+ky)*Ww + 2*px + kx];
}

// ---------------------------------------------------------------------------
// GroupNorm + GELU (unchanged; cross-round clock canary)
// ---------------------------------------------------------------------------
__global__ void gn_gelu_kernel(float* __restrict__ t, const float* __restrict__ w,
                               const float* __restrict__ b)
{
    int bb = blockIdx.x >> 5, g = blockIdx.x & 31;
    float* base = t + ((long)bb*Cc + g*16)*N2;
    int tid = threadIdx.x;
    float s = 0.0f, s2 = 0.0f;
    for (int i = tid; i < 16*N2; i += 256) { float v = base[i]; s += v; s2 += v*v; }
    __shared__ float r1[256], r2[256];
    r1[tid] = s; r2[tid] = s2;
    __syncthreads();
    for (int o = 128; o > 0; o >>= 1) {
        if (tid < o) { r1[tid] += r1[tid+o]; r2[tid] += r2[tid+o]; }
        __syncthreads();
    }
    float mu  = r1[0] * (1.0f/16384.0f);
    float var = r2[0] * (1.0f/16384.0f) - mu*mu;
    float rstd = rsqrtf(var + 1e-5f);
    for (int i = tid; i < 16*N2; i += 256) {
        int c = g*16 + (i >> 10);
        float v = (base[i] - mu) * rstd * w[c] + b[c];
        base[i] = 0.5f * v * (1.0f + erff(v * 0.70710678118654752f));
    }
}

// ---------------------------------------------------------------------------
// offset conv + reference grid + clip (unchanged)
// ---------------------------------------------------------------------------
__global__ void offset_pos_kernel(const float* __restrict__ t, const float* __restrict__ w2,
                                  float* __restrict__ pos)
{
    int gid = blockIdx.x * 8 + (threadIdx.x >> 5);
    int lane = threadIdx.x & 31;
    int b = gid >> 10, n = gid & 1023;
    const float* tb = t + (long)b*Cc*N2 + n;
    float sy = 0.0f, sx = 0.0f;
    for (int c = lane; c < Cc; c += 32) {
        float tv = tb[(long)c*N2];
        sy += w2[c]      * tv;
        sx += w2[Cc + c] * tv;
    }
#pragma unroll
    for (int o = 16; o > 0; o >>= 1) {
        sy += __shfl_down_sync(0xffffffffu, sy, o);
        sx += __shfl_down_sync(0xffffffffu, sx, o);
    }
    if (lane == 0) {
        int iy = n >> 5, ix = n & 31;
        float ry = (0.5f + (float)iy) / 31.0f * 2.0f - 1.0f;
        float rx = (0.5f + (float)ix) / 31.0f * 2.0f - 1.0f;
        pos[gid*2+0] = fminf(fmaxf(sy + ry, -1.0f), 1.0f);
        pos[gid*2+1] = fminf(fmaxf(sx + rx, -1.0f), 1.0f);
    }
}

// ---------------------------------------------------------------------------
// Bilinear grid_sample (unchanged)
// ---------------------------------------------------------------------------
__global__ void sample_kernel(const float* __restrict__ x, const float* __restrict__ pos,
                              float* __restrict__ sm)
{
    int gid = blockIdx.x;
    int b = gid >> 10, n = gid & 1023;
    float py = pos[gid*2+0], px = pos[gid*2+1];
    float fx = (px + 1.0f) * 0.5f * 63.0f;
    float fy = (py + 1.0f) * 0.5f * 63.0f;
    float x0f = floorf(fx), y0f = floorf(fy);
    float wx = fx - x0f, wy = fy - y0f;
    int x0 = min(max((int)x0f, 0), 63), y0 = min(max((int)y0f, 0), 63);
    int x1 = min(x0+1, 63), y1 = min(y0+1, 63);
    float w00 = (1.0f-wx)*(1.0f-wy), w01 = wx*(1.0f-wy);
    float w10 = (1.0f-wx)*wy,        w11 = wx*wy;
    const float* xb = x + (long)b*Cc*Ll;
    for (int c = threadIdx.x; c < Cc; c += 128) {
        const float* xc = xb + (long)c*Ll;
        float v = xc[y0*64+x0]*w00 + xc[y0*64+x1]*w01
                + xc[y1*64+x0]*w10 + xc[y1*64+x1]*w11;
        sm[((long)b*Cc + c)*N2 + n] = v;
    }
}

// ---------------------------------------------------------------------------
// Fused attention v2 (unchanged from R16): tensor-core QK^T + scalar
// softmax/RPE + FFMA2 PV.
// ---------------------------------------------------------------------------
#define SMEM_ATTN 59904
__global__ __launch_bounds__(128, 2)
void attn_kernel(const float* __restrict__ q, const float* __restrict__ kv,
                 const float* __restrict__ pos, const float* __restrict__ rpe,
                 float* __restrict__ out)
{
    extern __shared__ __align__(16) char smem[];
    unsigned* Qs = (unsigned*)(smem);            // [64][136] (init phase)
    unsigned* Kd = (unsigned*)(smem);            // [64][40]  (main phase)
    float*    Ss = (float*)(smem + 10240);       // [128][33]
    float*    Vs = (float*)(smem + 34816);       // [32][68]
    float*    rs = (float*)(smem + 43520);       // [63*63]
    float*    ps = (float*)(smem + 59396);       // [64]

    int bh = blockIdx.y; int b = bh >> 3, h = bh & 7;
    int tid = threadIdx.x;
    int m = blockIdx.x * 128 + tid;
    int w = tid >> 5, lane = tid & 31;
    int wm = w << 5, grp = lane >> 2, tig = lane & 3;

    const float* rh = rpe + h*Rr*Rr;
    for (int i = tid; i < Rr*Rr; i += 128) rs[i] = rh[i];

    const float* qbase = q + ((long)b*Cc + h*DK)*Ll + blockIdx.x*128;
    for (int e = tid; e < 64*128; e += 128) {
        int d = e >> 7, ml = e & 127;
        Qs[d*136 + ml] = cvt_tf32(qbase[(long)d*Ll + ml] * ATT_SCALE);
    }
    __syncthreads();
    unsigned af[8][2][4];
#pragma unroll
    for (int ks = 0; ks < 8; ks++) {
        int kb = ks << 3;
#pragma unroll
        for (int mt = 0; mt < 2; mt++) {
            int mr = wm + (mt << 4) + grp;
            af[ks][mt][0] = Qs[(kb+tig  )*136 + mr];
            af[ks][mt][1] = Qs[(kb+tig  )*136 + mr+8];
            af[ks][mt][2] = Qs[(kb+tig+4)*136 + mr];
            af[ks][mt][3] = Qs[(kb+tig+4)*136 + mr+8];
        }
    }
    float qgy = (float)(m >> 6) / 63.0f * 2.0f - 1.0f;
    float qgx = (float)(m & 63) / 63.0f * 2.0f - 1.0f;

    u64 ac2[32] = {};
    float runM = -1e30f, Z = 0.0f;

    const float* kbase = kv + ((long)b*2*Cc + h*DK)*N2;
    const float* vbase = kbase + (long)Cc*N2;
    const float* pb = pos + b*N2*2;

    for (int n0 = 0; n0 < N2; n0 += 32) {
        __syncthreads();
        for (int e = tid; e < 2048; e += 128) {
            int d = e >> 5, j = e & 31;
            Kd[d*40 + j] = cvt_tf32(kbase[d*N2 + n0 + j]);
            Vs[j*68 + d] = vbase[d*N2 + n0 + j];
        }
        if (tid < 64) ps[tid] = pb[n0*2 + tid];
        __syncthreads();

        float sacc[2][4][4] = {};
#pragma unroll
        for (int ks = 0; ks < 8; ks++) {
            int kb = ks << 3;
            unsigned bf[4][2];
#pragma unroll
            for (int nt = 0; nt < 4; nt++) {
                int nc = (nt << 3) + grp;
                bf[nt][0] = Kd[(kb+tig  )*40 + nc];
                bf[nt][1] = Kd[(kb+tig+4)*40 + nc];
            }
#pragma unroll
            for (int mt = 0; mt < 2; mt++)
#pragma unroll
                for (int nt = 0; nt < 4; nt++)
                    mma8(sacc[mt][nt], af[ks][mt], bf[nt]);
        }
#pragma unroll
        for (int mt = 0; mt < 2; mt++)
#pragma unroll
        for (int nt = 0; nt < 4; nt++) {
            int row = wm + (mt << 4) + grp;
            int col = (nt << 3) + (tig << 1);
            Ss[row*33 + col]       = sacc[mt][nt][0];
            Ss[row*33 + col+1]     = sacc[mt][nt][1];
            Ss[(row+8)*33 + col]   = sacc[mt][nt][2];
            Ss[(row+8)*33 + col+1] = sacc[mt][nt][3];
        }
        __syncwarp();

        for (int j = 0; j < 32; j++) {
            float dot = Ss[tid*33 + j];
            float dy = (qgy - ps[j*2+0]) * 0.5f;
            float dx = (qgx - ps[j*2+1]) * 0.5f;
            float fy = (dy + 1.0f) * 0.5f * 62.0f;
            float fx = (dx + 1.0f) * 0.5f * 62.0f;
            float y0f = floorf(fy), x0f = floorf(fx);
            float wy = fy - y0f, wx = fx - x0f;
            int y0 = min(max((int)y0f, 0), 62);
            int x0 = min(max((int)x0f, 0), 62);
            int y1 = min(y0 + 1, 62), x1 = min(x0 + 1, 62);
            float r00 = rs[y0*63+x0], r01 = rs[y0*63+x1];
            float r10 = rs[y1*63+x0], r11 = rs[y1*63+x1];
            float bia = r00*(1.0f-wx)*(1.0f-wy) + r01*wx*(1.0f-wy)
                      + r10*(1.0f-wx)*wy       + r11*wx*wy;
            float s = dot + bia;
            if (s > runM) {
                float corr = __expf(runM - s);
                Z *= corr;
                u64 c2 = pack2(corr, corr);
#pragma unroll
                for (int c = 0; c < 32; c++) fmul2(ac2[c], c2);
                runM = s;
            }
            float p = __expf(s - runM);
            Z += p;
            u64 p2 = pack2(p, p);
            const ulonglong2* vp = (const ulonglong2*)(Vs + j*68);
#pragma unroll
            for (int t = 0; t < 16; t++) {
                ulonglong2 vv = vp[t];
                ffma2(ac2[2*t],   p2, vv.x);
                ffma2(ac2[2*t+1], p2, vv.y);
            }
        }
    }
    float inv = 1.0f / Z;
    float* ob = out + ((long)b*Cc + h*DK)*Ll + m;
#pragma unroll
    for (int d2 = 0; d2 < 32; d2++) {
        float2 v = unpack2(ac2[d2]);
        ob[(long)(2*d2+0)*Ll] = v.x * inv;
        ob[(long)(2*d2+1)*Ll] = v.y * inv;
    }
}

// ---------------------------------------------------------------------------
extern "C" void kernel_launch(void* const* d_in, const int* in_sizes, int n_in,
                              void* d_out, int out_size)
{
    const float* x      = (const float*)d_in[0];
    const float* q_w    = (const float*)d_in[1];
    const float* q_b    = (const float*)d_in[2];
    const float* kv_w   = (const float*)d_in[3];
    const float* kv_b   = (const float*)d_in[4];
    const float* off1_w = (const float*)d_in[5];
    const float* off1_b = (const float*)d_in[6];
    const float* gn_w   = (const float*)d_in[7];
    const float* gn_b   = (const float*)d_in[8];
    const float* off2_w = (const float*)d_in[9];
    const float* rpe    = (const float*)d_in[10];
    const float* proj_w = (const float*)d_in[11];
    const float* proj_b = (const float*)d_in[12];
    float* out = (float*)d_out;

    float *gq, *gim, *gt, *gpos, *gsm, *gkv, *gao;
    cudaGetSymbolAddress((void**)&gq,   g_q);
    cudaGetSymbolAddress((void**)&gim,  g_im);
    cudaGetSymbolAddress((void**)&gt,   g_t);
    cudaGetSymbolAddress((void**)&gpos, g_pos);
    cudaGetSymbolAddress((void**)&gsm,  g_sm);
    cudaGetSymbolAddress((void**)&gkv,  g_kv);
    cudaGetSymbolAddress((void**)&gao,  g_ao);

    // >48KB dynamic smem; idempotent, capture-safe attribute sets.
    cudaFuncSetAttribute(attn_kernel, cudaFuncAttributeMaxDynamicSharedMemorySize,
                         SMEM_ATTN);
    cudaFuncSetAttribute(sgemm_bias, cudaFuncAttributeMaxDynamicSharedMemorySize,
                         SMEM_GEMM);

    // 0. dummy — keeps the fixed ncu capture slot on the off1 SGEMM below
    dummy_kernel<<<1,1>>>();
    // 1. q = conv1x1(x)
    sgemm_bias<<<dim3(64,4,2),256,SMEM_GEMM>>>(q_w, x, q_b, gq, 512, 4096, 512,
                                               (long)512*4096, (long)512*4096);
    // 2. im2col for 2x2 stride-2 conv
    im2col_kernel<<<16384,256>>>(gq, gim);
    // 3. t = conv2x2s2(q)   [ncu capture slot]
    sgemm_bias<<<dim3(16,4,2),256,SMEM_GEMM>>>(off1_w, gim, off1_b, gt, 512, 1024, 2048,
                                               (long)2048*1024, (long)512*1024);
    // 4. GroupNorm + GELU (in place)
    gn_gelu_kernel<<<64,256>>>(gt, gn_w, gn_b);
    // 5. offset conv + reference grid + clip -> pos
    offset_pos_kernel<<<256,256>>>(gt, off2_w, gpos);
    // 6. bilinear sample of x at pos
    sample_kernel<<<2048,128>>>(x, gpos, gsm);
    // 7. kv = conv1x1(sampled)
    sgemm_bias<<<dim3(16,8,2),256,SMEM_GEMM>>>(kv_w, gsm, kv_b, gkv, 1024, 1024, 512,
                                               (long)512*1024, (long)1024*1024);
    // 8. fused attention (tensor-core QK^T + RPE bias + softmax + PV)
    attn_kernel<<<dim3(32,16),128,SMEM_ATTN>>>(gq, gkv, gpos, rpe, gao);
    // 9. proj conv -> d_out
    sgemm_bias<<<dim3(64,4,2),256,SMEM_GEMM>>>(proj_w, gao, proj_b, out, 512, 4096, 512,
                                               (long)512*4096, (long)512*4096);
}